// round 1
// baseline (speedup 1.0000x reference)
#include <cuda_runtime.h>
#include <cuda_bf16.h>
#include <math.h>

// Problem shape (fixed by reference setup_inputs)
#define B_   2
#define S_   2048
#define D_   1024
#define H_   16
#define HD_  64
#define F_   4096
#define M_   (B_*S_)   // 4096 rows

// ---------------- scratch (device globals; no allocation allowed) ----------
__device__ float g_xn [M_*D_];   // layernorm output
__device__ float g_q  [M_*D_];
__device__ float g_k  [M_*D_];
__device__ float g_v  [M_*D_];
__device__ float g_att[M_*D_];   // attention output (pre O-proj)
__device__ float g_x2 [M_*D_];   // residual after attention block
__device__ float g_h  [M_*F_];   // FFN hidden

// ---------------- layernorm ------------------------------------------------
// One block per row. 256 threads, 4 floats each (D=1024).
__global__ __launch_bounds__(256) void ln_kernel(
    const float* __restrict__ x, const float* __restrict__ g,
    const float* __restrict__ b, float* __restrict__ out)
{
    __shared__ float red[8];
    const int row = blockIdx.x;
    const int tid = threadIdx.x;
    const float* xr = x + (long)row * D_;

    float4 xv = *(const float4*)(xr + tid * 4);

    // sum
    float s = xv.x + xv.y + xv.z + xv.w;
    #pragma unroll
    for (int o = 16; o > 0; o >>= 1) s += __shfl_xor_sync(0xffffffffu, s, o);
    if ((tid & 31) == 0) red[tid >> 5] = s;
    __syncthreads();
    float tot = 0.f;
    #pragma unroll
    for (int w = 0; w < 8; w++) tot += red[w];
    const float mean = tot * (1.0f / D_);

    float d0 = xv.x - mean, d1 = xv.y - mean, d2 = xv.z - mean, d3 = xv.w - mean;
    float sq = d0*d0 + d1*d1 + d2*d2 + d3*d3;
    __syncthreads();
    #pragma unroll
    for (int o = 16; o > 0; o >>= 1) sq += __shfl_xor_sync(0xffffffffu, sq, o);
    if ((tid & 31) == 0) red[tid >> 5] = sq;
    __syncthreads();
    float vtot = 0.f;
    #pragma unroll
    for (int w = 0; w < 8; w++) vtot += red[w];
    const float rstd = rsqrtf(vtot * (1.0f / D_) + 1e-5f);

    float4 gv = *(const float4*)(g + tid * 4);
    float4 bv = *(const float4*)(b + tid * 4);
    float4 o4;
    o4.x = d0 * rstd * gv.x + bv.x;
    o4.y = d1 * rstd * gv.y + bv.y;
    o4.z = d2 * rstd * gv.z + bv.z;
    o4.w = d3 * rstd * gv.w + bv.w;
    *(float4*)(out + (long)row * D_ + tid * 4) = o4;
}

// ---------------- SGEMM: C = act(A[M,K] @ W[K,N] + bias [+ res]) -----------
// 128x128 block tile, BK=8, 256 threads, 8x8 per thread.
#define BM 128
#define BN 128
#define BK 8

template<bool RELU, bool RES>
__global__ __launch_bounds__(256) void sgemm_kernel(
    const float* __restrict__ A, const float* __restrict__ W,
    const float* __restrict__ bias, const float* __restrict__ res,
    float* __restrict__ C, int M, int N, int K)
{
    __shared__ float Ast[BK][BM];
    __shared__ float Bs [BK][BN];

    const int tid = threadIdx.x;
    const int bm  = blockIdx.y * BM;
    const int bn  = blockIdx.x * BN;
    const int tx  = tid & 15;   // 0..15 -> cols
    const int ty  = tid >> 4;   // 0..15 -> rows

    // load indices
    const int ar = tid >> 1;          // 0..127 (A row)
    const int ac = (tid & 1) * 4;     // 0 or 4 (A col group)
    const int br = tid >> 5;          // 0..7   (B row)
    const int bc = (tid & 31) * 4;    // 0..124 (B col)

    float acc[8][8];
    #pragma unroll
    for (int i = 0; i < 8; i++)
        #pragma unroll
        for (int j = 0; j < 8; j++) acc[i][j] = 0.f;

    const float* Ap = A + (long)(bm + ar) * K + ac;
    const float* Wp = W + (long)br * N + bn + bc;

    for (int k0 = 0; k0 < K; k0 += BK) {
        float4 a4 = *(const float4*)(Ap + k0);
        Ast[ac + 0][ar] = a4.x;
        Ast[ac + 1][ar] = a4.y;
        Ast[ac + 2][ar] = a4.z;
        Ast[ac + 3][ar] = a4.w;
        *(float4*)&Bs[br][bc] = *(const float4*)(Wp + (long)k0 * N);
        __syncthreads();

        #pragma unroll
        for (int kk = 0; kk < BK; kk++) {
            float4 a0 = *(const float4*)&Ast[kk][ty * 8];
            float4 a1 = *(const float4*)&Ast[kk][ty * 8 + 4];
            float4 b0 = *(const float4*)&Bs [kk][tx * 8];
            float4 b1 = *(const float4*)&Bs [kk][tx * 8 + 4];
            float a[8] = {a0.x, a0.y, a0.z, a0.w, a1.x, a1.y, a1.z, a1.w};
            float b[8] = {b0.x, b0.y, b0.z, b0.w, b1.x, b1.y, b1.z, b1.w};
            #pragma unroll
            for (int i = 0; i < 8; i++)
                #pragma unroll
                for (int j = 0; j < 8; j++)
                    acc[i][j] += a[i] * b[j];
        }
        __syncthreads();
    }

    #pragma unroll
    for (int i = 0; i < 8; i++) {
        const long row = bm + ty * 8 + i;
        #pragma unroll
        for (int j = 0; j < 8; j += 4) {
            const long col = bn + tx * 8 + j;
            float4 o;
            o.x = acc[i][j + 0] + bias[col + 0];
            o.y = acc[i][j + 1] + bias[col + 1];
            o.z = acc[i][j + 2] + bias[col + 2];
            o.w = acc[i][j + 3] + bias[col + 3];
            if (RELU) {
                o.x = fmaxf(o.x, 0.f); o.y = fmaxf(o.y, 0.f);
                o.z = fmaxf(o.z, 0.f); o.w = fmaxf(o.w, 0.f);
            }
            if (RES) {
                const float4 r4 = *(const float4*)(res + row * N + col);
                o.x += r4.x; o.y += r4.y; o.z += r4.z; o.w += r4.w;
            }
            *(float4*)(C + row * N + col) = o;
        }
    }
}

// ---------------- fused attention ------------------------------------------
// Q,K,V laid out [B*S, D] with head h at columns [h*64, (h+1)*64).
// One thread = one query row; 128 queries per block; K/V tiles of 64 in smem.
// Online softmax with lazy rescale (only when running max changes).
__global__ __launch_bounds__(128) void attn_kernel(
    const float* __restrict__ Q, const float* __restrict__ K,
    const float* __restrict__ V, const int* __restrict__ mask,
    float* __restrict__ O)
{
    __shared__ float kt[64][64];
    __shared__ float vt[64][64];
    __shared__ int   ms[64];

    const int tid = threadIdx.x;
    const int qi  = blockIdx.x * 128 + tid;  // query index within sequence
    const int h   = blockIdx.y;
    const int b   = blockIdx.z;

    // load q into registers, pre-scaled by 1/sqrt(hd)=0.125
    float q[64];
    {
        const float* qp = Q + ((long)(b * S_ + qi)) * D_ + h * HD_;
        #pragma unroll
        for (int d = 0; d < 64; d += 4) {
            float4 t4 = *(const float4*)(qp + d);
            q[d + 0] = t4.x * 0.125f;
            q[d + 1] = t4.y * 0.125f;
            q[d + 2] = t4.z * 0.125f;
            q[d + 3] = t4.w * 0.125f;
        }
    }

    float m = -INFINITY, l = 0.f;
    float acc[64];
    #pragma unroll
    for (int d = 0; d < 64; d++) acc[d] = 0.f;

    for (int j0 = 0; j0 < S_; j0 += 64) {
        __syncthreads();
        // cooperative K/V tile load: 64x64 floats each = 1024 float4s per tile
        for (int t = tid; t < 1024; t += 128) {
            const int r = t >> 4;
            const int c = (t & 15) << 2;
            const long base = ((long)(b * S_ + j0 + r)) * D_ + h * HD_ + c;
            *(float4*)&kt[r][c] = *(const float4*)(K + base);
            *(float4*)&vt[r][c] = *(const float4*)(V + base);
        }
        if (tid < 64) ms[tid] = mask[b * S_ + j0 + tid];
        __syncthreads();

        for (int j = 0; j < 64; j++) {
            if (ms[j] == 0) continue;
            float s = 0.f;
            #pragma unroll
            for (int d = 0; d < 64; d += 4) {
                const float4 kk = *(const float4*)&kt[j][d];
                s += q[d] * kk.x + q[d + 1] * kk.y
                   + q[d + 2] * kk.z + q[d + 3] * kk.w;
            }
            if (s > m) {
                const float corr = __expf(m - s);
                l *= corr;
                #pragma unroll
                for (int d = 0; d < 64; d++) acc[d] *= corr;
                m = s;
            }
            const float p = __expf(s - m);
            l += p;
            #pragma unroll
            for (int d = 0; d < 64; d += 4) {
                const float4 vv = *(const float4*)&vt[j][d];
                acc[d + 0] += p * vv.x;
                acc[d + 1] += p * vv.y;
                acc[d + 2] += p * vv.z;
                acc[d + 3] += p * vv.w;
            }
        }
    }

    const float inv = (l > 0.f) ? 1.f / l : 0.f;
    float* op = O + ((long)(b * S_ + qi)) * D_ + h * HD_;
    #pragma unroll
    for (int d = 0; d < 64; d += 4) {
        float4 o4;
        o4.x = acc[d + 0] * inv;
        o4.y = acc[d + 1] * inv;
        o4.z = acc[d + 2] * inv;
        o4.w = acc[d + 3] * inv;
        *(float4*)(op + d) = o4;
    }
}

// ---------------- launch ----------------------------------------------------
extern "C" void kernel_launch(void* const* d_in, const int* in_sizes, int n_in,
                              void* d_out, int out_size)
{
    const float* x    = (const float*)d_in[0];
    const int*   mask = (const int*)  d_in[1];
    const float* wq   = (const float*)d_in[2];
    const float* bq   = (const float*)d_in[3];
    const float* wk   = (const float*)d_in[4];
    const float* bk   = (const float*)d_in[5];
    const float* wv   = (const float*)d_in[6];
    const float* bv   = (const float*)d_in[7];
    const float* wo   = (const float*)d_in[8];
    const float* bo   = (const float*)d_in[9];
    const float* g1   = (const float*)d_in[10];
    const float* be1  = (const float*)d_in[11];
    const float* g2   = (const float*)d_in[12];
    const float* be2  = (const float*)d_in[13];
    const float* w1   = (const float*)d_in[14];
    const float* bf1  = (const float*)d_in[15];
    const float* w2   = (const float*)d_in[16];
    const float* bf2  = (const float*)d_in[17];
    float* out = (float*)d_out;

    void* p;
    cudaGetSymbolAddress(&p, g_xn);  float* xn  = (float*)p;
    cudaGetSymbolAddress(&p, g_q);   float* qb  = (float*)p;
    cudaGetSymbolAddress(&p, g_k);   float* kb  = (float*)p;
    cudaGetSymbolAddress(&p, g_v);   float* vb  = (float*)p;
    cudaGetSymbolAddress(&p, g_att); float* att = (float*)p;
    cudaGetSymbolAddress(&p, g_x2);  float* x2  = (float*)p;
    cudaGetSymbolAddress(&p, g_h);   float* hb  = (float*)p;

    const dim3 gemmD (D_ / BN, M_ / BM);   // N=1024
    const dim3 gemmF (F_ / BN, M_ / BM);   // N=4096

    // 1) LN1
    ln_kernel<<<M_, 256>>>(x, g1, be1, xn);
    // 2) Q,K,V projections
    sgemm_kernel<false, false><<<gemmD, 256>>>(xn, wq, bq, nullptr, qb, M_, D_, D_);
    sgemm_kernel<false, false><<<gemmD, 256>>>(xn, wk, bk, nullptr, kb, M_, D_, D_);
    sgemm_kernel<false, false><<<gemmD, 256>>>(xn, wv, bv, nullptr, vb, M_, D_, D_);
    // 3) attention
    dim3 attG(S_ / 128, H_, B_);
    attn_kernel<<<attG, 128>>>(qb, kb, vb, mask, att);
    // 4) output projection + residual
    sgemm_kernel<false, true><<<gemmD, 256>>>(att, wo, bo, x, x2, M_, D_, D_);
    // 5) LN2
    ln_kernel<<<M_, 256>>>(x2, g2, be2, xn);
    // 6) FFN
    sgemm_kernel<true, false><<<gemmF, 256>>>(xn, w1, bf1, nullptr, hb, M_, F_, D_);
    sgemm_kernel<false, true><<<gemmD, 256>>>(hb, w2, bf2, x2, out, M_, D_, F_);
}

// round 3
// speedup vs baseline: 1.7109x; 1.7109x over previous
#include <cuda_runtime.h>
#include <cuda_bf16.h>
#include <math.h>

typedef unsigned int u32;
typedef unsigned long long u64;
using bf16 = __nv_bfloat16;

#define B_   2
#define S_   2048
#define D_   1024
#define H_   16
#define F_   4096
#define M_   (B_*S_)

// ------------------------- scratch (device globals) -------------------------
__device__ __align__(16) bf16  g_xnh[M_*D_],  g_xnl[M_*D_];
__device__ __align__(16) float g_q[M_*D_], g_k[M_*D_], g_v[M_*D_];
__device__ __align__(16) bf16  g_atth[M_*D_], g_attl[M_*D_];
__device__ __align__(16) float g_x2[M_*D_];
__device__ __align__(16) bf16  g_hh[(size_t)M_*F_], g_hl[(size_t)M_*F_];
// transposed split weights: [N, K] layout
__device__ __align__(16) bf16  g_wqh[D_*D_], g_wql[D_*D_];
__device__ __align__(16) bf16  g_wkh[D_*D_], g_wkl[D_*D_];
__device__ __align__(16) bf16  g_wvh[D_*D_], g_wvl[D_*D_];
__device__ __align__(16) bf16  g_woh[D_*D_], g_wol[D_*D_];
__device__ __align__(16) bf16  g_w1h[(size_t)F_*D_], g_w1l[(size_t)F_*D_];
__device__ __align__(16) bf16  g_w2h[(size_t)D_*F_], g_w2l[(size_t)D_*F_];

// ------------------------- helpers ------------------------------------------
__device__ __forceinline__ u32 smem_u32(const void* p) {
    u32 a;
    asm("{ .reg .u64 t; cvta.to.shared.u64 t, %1; cvt.u32.u64 %0, t; }"
        : "=r"(a) : "l"(p));
    return a;
}
#define CP_ASYNC16(sm, gp) \
    asm volatile("cp.async.cg.shared.global [%0], [%1], 16;" :: "r"(sm), "l"(gp))
#define CP_COMMIT() asm volatile("cp.async.commit_group;" ::: "memory")
#define CP_WAIT(n)  asm volatile("cp.async.wait_group %0;" :: "n"(n) : "memory")

#define LDSM_X4(r0,r1,r2,r3,a) \
    asm volatile("ldmatrix.sync.aligned.m8n8.x4.shared.b16 {%0,%1,%2,%3}, [%4];" \
        : "=r"(r0), "=r"(r1), "=r"(r2), "=r"(r3) : "r"(a))

#define MMA_BF16(d, a, b) \
    asm volatile("mma.sync.aligned.m16n8k16.row.col.f32.bf16.bf16.f32 " \
        "{%0,%1,%2,%3}, {%4,%5,%6,%7}, {%8,%9}, {%0,%1,%2,%3};" \
        : "+f"((d)[0]), "+f"((d)[1]), "+f"((d)[2]), "+f"((d)[3]) \
        : "r"((a)[0]), "r"((a)[1]), "r"((a)[2]), "r"((a)[3]), \
          "r"((b)[0]), "r"((b)[1]))

// packed f32x2
#define FMA2(d,a,b,c) asm("fma.rn.f32x2 %0, %1, %2, %3;" : "=l"(d) : "l"(a), "l"(b), "l"(c))
#define MUL2(d,a,b)   asm("mul.rn.f32x2 %0, %1, %2;" : "=l"(d) : "l"(a), "l"(b))
#define PK2(d,x,y)    asm("mov.b64 %0, {%1,%2};" : "=l"(d) : "f"(x), "f"(y))
#define UPK2(x,y,d)   asm("mov.b64 {%0,%1}, %2;" : "=f"(x), "=f"(y) : "l"(d))

__device__ __forceinline__ void split2(float v, bf16& h, bf16& l) {
    h = __float2bfloat16_rn(v);
    l = __float2bfloat16_rn(v - __bfloat162float(h));
}

// ------------------------- layernorm with split output ----------------------
__global__ __launch_bounds__(256) void ln_split_kernel(
    const float* __restrict__ x, const float* __restrict__ g,
    const float* __restrict__ b, bf16* __restrict__ oh, bf16* __restrict__ ol)
{
    __shared__ float red[8];
    const int row = blockIdx.x;
    const int tid = threadIdx.x;
    const float* xr = x + (size_t)row * D_;

    float4 xv = *(const float4*)(xr + tid * 4);
    float s = xv.x + xv.y + xv.z + xv.w;
    #pragma unroll
    for (int o = 16; o > 0; o >>= 1) s += __shfl_xor_sync(0xffffffffu, s, o);
    if ((tid & 31) == 0) red[tid >> 5] = s;
    __syncthreads();
    float tot = 0.f;
    #pragma unroll
    for (int w = 0; w < 8; w++) tot += red[w];
    const float mean = tot * (1.0f / D_);

    float d0 = xv.x - mean, d1 = xv.y - mean, d2 = xv.z - mean, d3 = xv.w - mean;
    float sq = d0*d0 + d1*d1 + d2*d2 + d3*d3;
    __syncthreads();
    #pragma unroll
    for (int o = 16; o > 0; o >>= 1) sq += __shfl_xor_sync(0xffffffffu, sq, o);
    if ((tid & 31) == 0) red[tid >> 5] = sq;
    __syncthreads();
    float vtot = 0.f;
    #pragma unroll
    for (int w = 0; w < 8; w++) vtot += red[w];
    const float rstd = rsqrtf(vtot * (1.0f / D_) + 1e-5f);

    float4 gv = *(const float4*)(g + tid * 4);
    float4 bv = *(const float4*)(b + tid * 4);
    float o0 = d0 * rstd * gv.x + bv.x;
    float o1 = d1 * rstd * gv.y + bv.y;
    float o2 = d2 * rstd * gv.z + bv.z;
    float o3 = d3 * rstd * gv.w + bv.w;

    bf16 h0,h1,h2,h3,l0,l1,l2,l3;
    split2(o0,h0,l0); split2(o1,h1,l1); split2(o2,h2,l2); split2(o3,h3,l3);
    const size_t off = (size_t)row * D_ + tid * 4;
    __nv_bfloat162 hp0; hp0.x=h0; hp0.y=h1;
    __nv_bfloat162 hp1; hp1.x=h2; hp1.y=h3;
    __nv_bfloat162 lp0; lp0.x=l0; lp0.y=l1;
    __nv_bfloat162 lp1; lp1.x=l2; lp1.y=l3;
    *(__nv_bfloat162*)(oh + off)     = hp0;
    *(__nv_bfloat162*)(oh + off + 2) = hp1;
    *(__nv_bfloat162*)(ol + off)     = lp0;
    *(__nv_bfloat162*)(ol + off + 2) = lp1;
}

// ------------------------- weight transpose + split -------------------------
__global__ __launch_bounds__(256) void tsplit_kernel(
    const float* __restrict__ W, bf16* __restrict__ Th, bf16* __restrict__ Tl,
    int K, int N)
{
    __shared__ float t[32][33];
    const int tx = threadIdx.x, ty = threadIdx.y;
    const int n0 = blockIdx.x * 32, k0 = blockIdx.y * 32;
    #pragma unroll
    for (int r = 0; r < 4; r++)
        t[ty + r*8][tx] = W[(size_t)(k0 + ty + r*8) * N + n0 + tx];
    __syncthreads();
    #pragma unroll
    for (int r = 0; r < 4; r++) {
        float v = t[tx][ty + r*8];
        bf16 h, l; split2(v, h, l);
        const size_t o = (size_t)(n0 + ty + r*8) * K + k0 + tx;
        Th[o] = h; Tl[o] = l;
    }
}

// ------------------------- HMMA split-bf16 GEMM -----------------------------
// C[M,N] = A[M,K] @ W[K,N]; A as (Ah+Al)[M,K], W^T as (Bh+Bl)[N,K].
// 128x128 CTA tile, BK=32 chunk, 8 warps (64x32 warp tiles), cp.async 2-stage.
// Smem tile: 128 rows x (32+8) bf16 (row stride 80 B, 16B-aligned, LDSM
// conflict-free). Per-stage: 4 tiles x 10240 B = 40960 B; 2 stages = 80 KB.
#define TROWB 80            // smem row stride in bytes
#define TILEB (128*TROWB)   // 10240
#define STAGEB (4*TILEB)    // 40960

template<bool RELU, bool RES, bool SPLIT>
__global__ __launch_bounds__(256) void hmma_gemm(
    const bf16* __restrict__ Ah, const bf16* __restrict__ Al,
    const bf16* __restrict__ Bh, const bf16* __restrict__ Bl,
    const float* __restrict__ bias, const float* __restrict__ res,
    float* __restrict__ C, bf16* __restrict__ Ch, bf16* __restrict__ Cl,
    int M, int N, int K)
{
    extern __shared__ char smem[];
    const u32 sbase = smem_u32(smem);

    const int tid = threadIdx.x;
    const int wid = tid >> 5;
    const int lid = tid & 31;
    const int wr  = wid & 1;        // 0..1 : 64-row group
    const int wc  = wid >> 1;       // 0..3 : 32-col group
    const int bm  = blockIdx.y * 128;
    const int bn  = blockIdx.x * 128;

    const bf16* srcs[4] = {Ah, Al, Bh, Bl};
    const int   rb  [4] = {bm, bm, bn, bn};

    const int nch = K >> 5;

    // per-thread load indices (8 segments of 16B per thread per stage)
    int l_tile[8], l_seg[8];
    size_t l_grow[8];
    u32 l_sm[8];
    #pragma unroll
    for (int it = 0; it < 8; it++) {
        const int idx = tid + it * 256;
        const int tile = idx >> 9;
        const int r    = (idx >> 2) & 127;
        const int seg  = idx & 3;
        l_tile[it] = tile;
        l_seg[it]  = seg;
        l_grow[it] = (size_t)(rb[tile] + r);
        l_sm[it]   = tile * TILEB + r * TROWB + seg * 16;
    }

    // issue loads for chunk i into stage st
    auto load_chunk = [&](int i, int st) {
        const size_t kc = (size_t)i * 32;
        const u32 so = sbase + st * STAGEB;
        #pragma unroll
        for (int it = 0; it < 8; it++) {
            const bf16* gp = srcs[l_tile[it]] + l_grow[it] * (size_t)K + kc + l_seg[it] * 8;
            CP_ASYNC16(so + l_sm[it], gp);
        }
        CP_COMMIT();
    };

    float acc[4][4][4];
    #pragma unroll
    for (int i = 0; i < 4; i++)
        #pragma unroll
        for (int j = 0; j < 4; j++)
            #pragma unroll
            for (int f = 0; f < 4; f++) acc[i][j][f] = 0.f;

    // ldmatrix base addresses (per lane), before k offset
    // A: row = wr*64 + am*16 + (lid&15); colseg = (lid>>4)*8
    // B: row = wc*32 + bt2*16 + (lid&15); same colseg
    const u32 a_lane = (u32)((wr*64 + (lid & 15)) * TROWB + (lid >> 4) * 16);
    const u32 b_lane = (u32)((wc*32 + (lid & 15)) * TROWB + (lid >> 4) * 16);

    load_chunk(0, 0);

    for (int i = 0; i < nch; i++) {
        const int st = i & 1;
        const bool has_next = (i + 1 < nch);
        if (has_next) load_chunk(i + 1, st ^ 1);
        if (has_next) { CP_WAIT(1); } else { CP_WAIT(0); }
        __syncthreads();

        const u32 so = sbase + st * STAGEB;
        const u32 aH = so + a_lane;              // Ah tile
        const u32 aL = so + TILEB + a_lane;      // Al tile
        const u32 bH = so + 2*TILEB + b_lane;    // Bh tile
        const u32 bL = so + 3*TILEB + b_lane;    // Bl tile

        #pragma unroll
        for (int ks = 0; ks < 2; ks++) {
            const u32 ko = ks * 32;  // 16 bf16 = 32 bytes

            u32 fAh[4][4], fAl[4][4];
            #pragma unroll
            for (int am = 0; am < 4; am++) {
                LDSM_X4(fAh[am][0], fAh[am][1], fAh[am][2], fAh[am][3],
                        aH + am * (16*TROWB) + ko);
                LDSM_X4(fAl[am][0], fAl[am][1], fAl[am][2], fAl[am][3],
                        aL + am * (16*TROWB) + ko);
            }
            u32 fBh[4][2], fBl[4][2];
            #pragma unroll
            for (int bt2 = 0; bt2 < 2; bt2++) {
                u32 r0, r1, r2, r3;
                LDSM_X4(r0, r1, r2, r3, bH + bt2 * (16*TROWB) + ko);
                fBh[bt2*2  ][0] = r0; fBh[bt2*2  ][1] = r2;
                fBh[bt2*2+1][0] = r1; fBh[bt2*2+1][1] = r3;
                LDSM_X4(r0, r1, r2, r3, bL + bt2 * (16*TROWB) + ko);
                fBl[bt2*2  ][0] = r0; fBl[bt2*2  ][1] = r2;
                fBl[bt2*2+1][0] = r1; fBl[bt2*2+1][1] = r3;
            }

            #pragma unroll
            for (int am = 0; am < 4; am++)
                #pragma unroll
                for (int bt = 0; bt < 4; bt++) {
                    MMA_BF16(acc[am][bt], fAh[am], fBh[bt]);
                    MMA_BF16(acc[am][bt], fAh[am], fBl[bt]);
                    MMA_BF16(acc[am][bt], fAl[am], fBh[bt]);
                }
        }
        __syncthreads();
    }

    // ----------------- epilogue -----------------
    const int r0 = bm + wr*64 + (lid >> 2);
    const int c0 = bn + wc*32 + (lid & 3) * 2;
    #pragma unroll
    for (int am = 0; am < 4; am++) {
        #pragma unroll
        for (int bt = 0; bt < 4; bt++) {
            const int col = c0 + bt * 8;
            const float2 bv = *(const float2*)(bias + col);
            #pragma unroll
            for (int half = 0; half < 2; half++) {
                const int row = r0 + am*16 + half*8;
                float v0 = acc[am][bt][half*2 + 0] + bv.x;
                float v1 = acc[am][bt][half*2 + 1] + bv.y;
                if (RELU) { v0 = fmaxf(v0, 0.f); v1 = fmaxf(v1, 0.f); }
                if (RES) {
                    const float2 rr = *(const float2*)(res + (size_t)row * N + col);
                    v0 += rr.x; v1 += rr.y;
                }
                if (SPLIT) {
                    bf16 h0, h1, l0, l1;
                    split2(v0, h0, l0); split2(v1, h1, l1);
                    __nv_bfloat162 hp; hp.x = h0; hp.y = h1;
                    __nv_bfloat162 lp; lp.x = l0; lp.y = l1;
                    *(__nv_bfloat162*)(Ch + (size_t)row * N + col) = hp;
                    *(__nv_bfloat162*)(Cl + (size_t)row * N + col) = lp;
                } else {
                    float2 o; o.x = v0; o.y = v1;
                    *(float2*)(C + (size_t)row * N + col) = o;
                }
            }
        }
    }
}

// ------------------------- fused attention (packed f32x2) -------------------
__global__ __launch_bounds__(128) void attn_kernel(
    const float* __restrict__ Q, const float* __restrict__ K,
    const float* __restrict__ V, const int* __restrict__ mask,
    bf16* __restrict__ Oh, bf16* __restrict__ Ol)
{
    __shared__ float kt[64][64];
    __shared__ float vt[64][64];
    __shared__ int   ms[64];

    const int tid = threadIdx.x;
    const int qi  = blockIdx.x * 128 + tid;
    const int h   = blockIdx.y;
    const int b   = blockIdx.z;

    u64 q2[32];
    {
        const float* qp = Q + ((size_t)(b * S_ + qi)) * D_ + h * 64;
        #pragma unroll
        for (int i = 0; i < 16; i++) {
            float4 t4 = *(const float4*)(qp + i * 4);
            t4.x *= 0.125f; t4.y *= 0.125f; t4.z *= 0.125f; t4.w *= 0.125f;
            PK2(q2[2*i],   t4.x, t4.y);
            PK2(q2[2*i+1], t4.z, t4.w);
        }
    }

    float m = -INFINITY, l = 0.f;
    u64 acc2[32];
    #pragma unroll
    for (int i = 0; i < 32; i++) acc2[i] = 0ull;

    for (int j0 = 0; j0 < S_; j0 += 64) {
        __syncthreads();
        for (int t = tid; t < 1024; t += 128) {
            const int r = t >> 4;
            const int c = (t & 15) << 2;
            const size_t base = ((size_t)(b * S_ + j0 + r)) * D_ + h * 64 + c;
            *(float4*)&kt[r][c] = *(const float4*)(K + base);
            *(float4*)&vt[r][c] = *(const float4*)(V + base);
        }
        if (tid < 64) ms[tid] = mask[b * S_ + j0 + tid];
        __syncthreads();

        for (int j = 0; j < 64; j++) {
            if (ms[j] == 0) continue;
            u64 s2a = 0ull, s2b = 0ull, s2c = 0ull, s2d = 0ull;
            const ulonglong2* kp = (const ulonglong2*)kt[j];
            #pragma unroll
            for (int dd = 0; dd < 16; dd += 2) {
                const ulonglong2 k0 = kp[dd];
                const ulonglong2 k1 = kp[dd + 1];
                FMA2(s2a, q2[2*dd    ], k0.x, s2a);
                FMA2(s2b, q2[2*dd + 1], k0.y, s2b);
                FMA2(s2c, q2[2*dd + 2], k1.x, s2c);
                FMA2(s2d, q2[2*dd + 3], k1.y, s2d);
            }
            float f0,f1,f2,f3,f4,f5,f6,f7;
            UPK2(f0, f1, s2a); UPK2(f2, f3, s2b);
            UPK2(f4, f5, s2c); UPK2(f6, f7, s2d);
            const float s = ((f0 + f1) + (f2 + f3)) + ((f4 + f5) + (f6 + f7));

            if (s > m) {
                const float corr = __expf(m - s);
                u64 c2; PK2(c2, corr, corr);
                l *= corr;
                #pragma unroll
                for (int i = 0; i < 32; i++) MUL2(acc2[i], acc2[i], c2);
                m = s;
            }
            const float p = __expf(s - m);
            l += p;
            u64 p2; PK2(p2, p, p);
            const ulonglong2* vp = (const ulonglong2*)vt[j];
            #pragma unroll
            for (int dd = 0; dd < 16; dd++) {
                const ulonglong2 vv = vp[dd];
                FMA2(acc2[2*dd],     p2, vv.x, acc2[2*dd]);
                FMA2(acc2[2*dd + 1], p2, vv.y, acc2[2*dd + 1]);
            }
        }
    }

    const float inv = (l > 0.f) ? 1.f / l : 0.f;
    const size_t obase = ((size_t)(b * S_ + qi)) * D_ + h * 64;
    #pragma unroll
    for (int i = 0; i < 32; i++) {
        float a0, a1;
        UPK2(a0, a1, acc2[i]);
        a0 *= inv; a1 *= inv;
        bf16 h0, h1, l0, l1;
        split2(a0, h0, l0); split2(a1, h1, l1);
        __nv_bfloat162 hp; hp.x = h0; hp.y = h1;
        __nv_bfloat162 lp; lp.x = l0; lp.y = l1;
        *(__nv_bfloat162*)(Oh + obase + 2*i) = hp;
        *(__nv_bfloat162*)(Ol + obase + 2*i) = lp;
    }
}

// ------------------------- launch -------------------------------------------
#define GSMEM (2*STAGEB)

extern "C" void kernel_launch(void* const* d_in, const int* in_sizes, int n_in,
                              void* d_out, int out_size)
{
    const float* x    = (const float*)d_in[0];
    const int*   mask = (const int*)  d_in[1];
    const float* wq   = (const float*)d_in[2];
    const float* bq   = (const float*)d_in[3];
    const float* wk   = (const float*)d_in[4];
    const float* bk   = (const float*)d_in[5];
    const float* wv   = (const float*)d_in[6];
    const float* bv   = (const float*)d_in[7];
    const float* wo   = (const float*)d_in[8];
    const float* bo   = (const float*)d_in[9];
    const float* g1   = (const float*)d_in[10];
    const float* be1  = (const float*)d_in[11];
    const float* g2   = (const float*)d_in[12];
    const float* be2  = (const float*)d_in[13];
    const float* w1   = (const float*)d_in[14];
    const float* bf1  = (const float*)d_in[15];
    const float* w2   = (const float*)d_in[16];
    const float* bf2  = (const float*)d_in[17];
    float* out = (float*)d_out;

    void* p;
    cudaGetSymbolAddress(&p, g_xnh);  bf16* xnh = (bf16*)p;
    cudaGetSymbolAddress(&p, g_xnl);  bf16* xnl = (bf16*)p;
    cudaGetSymbolAddress(&p, g_q);    float* qb = (float*)p;
    cudaGetSymbolAddress(&p, g_k);    float* kb = (float*)p;
    cudaGetSymbolAddress(&p, g_v);    float* vb = (float*)p;
    cudaGetSymbolAddress(&p, g_atth); bf16* ath = (bf16*)p;
    cudaGetSymbolAddress(&p, g_attl); bf16* atl = (bf16*)p;
    cudaGetSymbolAddress(&p, g_x2);   float* x2 = (float*)p;
    cudaGetSymbolAddress(&p, g_hh);   bf16* hh  = (bf16*)p;
    cudaGetSymbolAddress(&p, g_hl);   bf16* hl  = (bf16*)p;
    cudaGetSymbolAddress(&p, g_wqh);  bf16* wqh = (bf16*)p;
    cudaGetSymbolAddress(&p, g_wql);  bf16* wql = (bf16*)p;
    cudaGetSymbolAddress(&p, g_wkh);  bf16* wkh = (bf16*)p;
    cudaGetSymbolAddress(&p, g_wkl);  bf16* wkl = (bf16*)p;
    cudaGetSymbolAddress(&p, g_wvh);  bf16* wvh = (bf16*)p;
    cudaGetSymbolAddress(&p, g_wvl);  bf16* wvl = (bf16*)p;
    cudaGetSymbolAddress(&p, g_woh);  bf16* woh = (bf16*)p;
    cudaGetSymbolAddress(&p, g_wol);  bf16* wol = (bf16*)p;
    cudaGetSymbolAddress(&p, g_w1h);  bf16* w1h = (bf16*)p;
    cudaGetSymbolAddress(&p, g_w1l);  bf16* w1l = (bf16*)p;
    cudaGetSymbolAddress(&p, g_w2h);  bf16* w2h = (bf16*)p;
    cudaGetSymbolAddress(&p, g_w2l);  bf16* w2l = (bf16*)p;

    cudaFuncSetAttribute(hmma_gemm<false,false,false>, cudaFuncAttributeMaxDynamicSharedMemorySize, GSMEM);
    cudaFuncSetAttribute(hmma_gemm<false,true ,false>, cudaFuncAttributeMaxDynamicSharedMemorySize, GSMEM);
    cudaFuncSetAttribute(hmma_gemm<true ,false,true >, cudaFuncAttributeMaxDynamicSharedMemorySize, GSMEM);

    const dim3 tb(32, 8);
    tsplit_kernel<<<dim3(D_/32, D_/32), tb>>>(wq, wqh, wql, D_, D_);
    tsplit_kernel<<<dim3(D_/32, D_/32), tb>>>(wk, wkh, wkl, D_, D_);
    tsplit_kernel<<<dim3(D_/32, D_/32), tb>>>(wv, wvh, wvl, D_, D_);
    tsplit_kernel<<<dim3(D_/32, D_/32), tb>>>(wo, woh, wol, D_, D_);
    tsplit_kernel<<<dim3(F_/32, D_/32), tb>>>(w1, w1h, w1l, D_, F_);
    tsplit_kernel<<<dim3(D_/32, F_/32), tb>>>(w2, w2h, w2l, F_, D_);

    ln_split_kernel<<<M_, 256>>>(x, g1, be1, xnh, xnl);

    const dim3 gD(D_/128, M_/128);
    hmma_gemm<false,false,false><<<gD, 256, GSMEM>>>(xnh, xnl, wqh, wql, bq, nullptr, qb, nullptr, nullptr, M_, D_, D_);
    hmma_gemm<false,false,false><<<gD, 256, GSMEM>>>(xnh, xnl, wkh, wkl, bk, nullptr, kb, nullptr, nullptr, M_, D_, D_);
    hmma_gemm<false,false,false><<<gD, 256, GSMEM>>>(xnh, xnl, wvh, wvl, bv, nullptr, vb, nullptr, nullptr, M_, D_, D_);

    dim3 attG(S_/128, H_, B_);
    attn_kernel<<<attG, 128>>>(qb, kb, vb, mask, ath, atl);

    hmma_gemm<false,true,false><<<gD, 256, GSMEM>>>(ath, atl, woh, wol, bo, x, x2, nullptr, nullptr, M_, D_, D_);

    ln_split_kernel<<<M_, 256>>>(x2, g2, be2, xnh, xnl);

    const dim3 gF(F_/128, M_/128);
    hmma_gemm<true,false,true><<<gF, 256, GSMEM>>>(xnh, xnl, w1h, w1l, bf1, nullptr, nullptr, hh, hl, M_, F_, D_);

    hmma_gemm<false,true,false><<<gD, 256, GSMEM>>>(hh, hl, w2h, w2l, bf2, x2, out, nullptr, nullptr, M_, D_, F_);
}

// round 4
// speedup vs baseline: 2.8641x; 1.6740x over previous
#include <cuda_runtime.h>
#include <cuda_bf16.h>
#include <math.h>

typedef unsigned int u32;
typedef unsigned long long u64;
using bf16 = __nv_bfloat16;

#define B_   2
#define S_   2048
#define D_   1024
#define H_   16
#define F_   4096
#define M_   (B_*S_)

// ------------------------- scratch (device globals) -------------------------
__device__ __align__(16) bf16  g_xnh[M_*D_],  g_xnl[M_*D_];
__device__ __align__(16) bf16  g_qb[M_*D_], g_kb[M_*D_], g_vb[M_*D_];
__device__ __align__(16) bf16  g_atth[M_*D_], g_attl[M_*D_];
__device__ __align__(16) float g_x2[M_*D_];
__device__ __align__(16) bf16  g_hh[(size_t)M_*F_], g_hl[(size_t)M_*F_];
__device__ __align__(16) bf16  g_wqh[D_*D_], g_wql[D_*D_];
__device__ __align__(16) bf16  g_wkh[D_*D_], g_wkl[D_*D_];
__device__ __align__(16) bf16  g_wvh[D_*D_], g_wvl[D_*D_];
__device__ __align__(16) bf16  g_woh[D_*D_], g_wol[D_*D_];
__device__ __align__(16) bf16  g_w1h[(size_t)F_*D_], g_w1l[(size_t)F_*D_];
__device__ __align__(16) bf16  g_w2h[(size_t)D_*F_], g_w2l[(size_t)D_*F_];

// ------------------------- helpers ------------------------------------------
__device__ __forceinline__ u32 smem_u32(const void* p) {
    u32 a;
    asm("{ .reg .u64 t; cvta.to.shared.u64 t, %1; cvt.u32.u64 %0, t; }"
        : "=r"(a) : "l"(p));
    return a;
}
#define CP_ASYNC16(sm, gp) \
    asm volatile("cp.async.cg.shared.global [%0], [%1], 16;" :: "r"(sm), "l"(gp))
#define CP_COMMIT() asm volatile("cp.async.commit_group;" ::: "memory")
#define CP_WAIT(n)  asm volatile("cp.async.wait_group %0;" :: "n"(n) : "memory")

#define LDSM_X4(r0,r1,r2,r3,a) \
    asm volatile("ldmatrix.sync.aligned.m8n8.x4.shared.b16 {%0,%1,%2,%3}, [%4];" \
        : "=r"(r0), "=r"(r1), "=r"(r2), "=r"(r3) : "r"(a))
#define LDSM_X4_T(r0,r1,r2,r3,a) \
    asm volatile("ldmatrix.sync.aligned.m8n8.x4.trans.shared.b16 {%0,%1,%2,%3}, [%4];" \
        : "=r"(r0), "=r"(r1), "=r"(r2), "=r"(r3) : "r"(a))

#define MMA_BF16(d, a, b) \
    asm volatile("mma.sync.aligned.m16n8k16.row.col.f32.bf16.bf16.f32 " \
        "{%0,%1,%2,%3}, {%4,%5,%6,%7}, {%8,%9}, {%0,%1,%2,%3};" \
        : "+f"((d)[0]), "+f"((d)[1]), "+f"((d)[2]), "+f"((d)[3]) \
        : "r"((a)[0]), "r"((a)[1]), "r"((a)[2]), "r"((a)[3]), \
          "r"((b)[0]), "r"((b)[1]))

__device__ __forceinline__ void split2(float v, bf16& h, bf16& l) {
    h = __float2bfloat16_rn(v);
    l = __float2bfloat16_rn(v - __bfloat162float(h));
}
__device__ __forceinline__ u32 pack_bf2(float a, float b) {
    __nv_bfloat162 t = __float22bfloat162_rn(make_float2(a, b));
    return *(u32*)&t;
}

// ------------------------- layernorm with split output ----------------------
__global__ __launch_bounds__(256) void ln_split_kernel(
    const float* __restrict__ x, const float* __restrict__ g,
    const float* __restrict__ b, bf16* __restrict__ oh, bf16* __restrict__ ol)
{
    __shared__ float red[8];
    const int row = blockIdx.x;
    const int tid = threadIdx.x;
    const float* xr = x + (size_t)row * D_;

    float4 xv = *(const float4*)(xr + tid * 4);
    float s = xv.x + xv.y + xv.z + xv.w;
    #pragma unroll
    for (int o = 16; o > 0; o >>= 1) s += __shfl_xor_sync(0xffffffffu, s, o);
    if ((tid & 31) == 0) red[tid >> 5] = s;
    __syncthreads();
    float tot = 0.f;
    #pragma unroll
    for (int w = 0; w < 8; w++) tot += red[w];
    const float mean = tot * (1.0f / D_);

    float d0 = xv.x - mean, d1 = xv.y - mean, d2 = xv.z - mean, d3 = xv.w - mean;
    float sq = d0*d0 + d1*d1 + d2*d2 + d3*d3;
    __syncthreads();
    #pragma unroll
    for (int o = 16; o > 0; o >>= 1) sq += __shfl_xor_sync(0xffffffffu, sq, o);
    if ((tid & 31) == 0) red[tid >> 5] = sq;
    __syncthreads();
    float vtot = 0.f;
    #pragma unroll
    for (int w = 0; w < 8; w++) vtot += red[w];
    const float rstd = rsqrtf(vtot * (1.0f / D_) + 1e-5f);

    float4 gv = *(const float4*)(g + tid * 4);
    float4 bv = *(const float4*)(b + tid * 4);
    float o0 = d0 * rstd * gv.x + bv.x;
    float o1 = d1 * rstd * gv.y + bv.y;
    float o2 = d2 * rstd * gv.z + bv.z;
    float o3 = d3 * rstd * gv.w + bv.w;

    bf16 h0,h1,h2,h3,l0,l1,l2,l3;
    split2(o0,h0,l0); split2(o1,h1,l1); split2(o2,h2,l2); split2(o3,h3,l3);
    const size_t off = (size_t)row * D_ + tid * 4;
    __nv_bfloat162 hp0; hp0.x=h0; hp0.y=h1;
    __nv_bfloat162 hp1; hp1.x=h2; hp1.y=h3;
    __nv_bfloat162 lp0; lp0.x=l0; lp0.y=l1;
    __nv_bfloat162 lp1; lp1.x=l2; lp1.y=l3;
    *(__nv_bfloat162*)(oh + off)     = hp0;
    *(__nv_bfloat162*)(oh + off + 2) = hp1;
    *(__nv_bfloat162*)(ol + off)     = lp0;
    *(__nv_bfloat162*)(ol + off + 2) = lp1;
}

// ------------------------- weight transpose + split -------------------------
__global__ __launch_bounds__(256) void tsplit_kernel(
    const float* __restrict__ W, bf16* __restrict__ Th, bf16* __restrict__ Tl,
    int K, int N)
{
    __shared__ float t[32][33];
    const int tx = threadIdx.x, ty = threadIdx.y;
    const int n0 = blockIdx.x * 32, k0 = blockIdx.y * 32;
    #pragma unroll
    for (int r = 0; r < 4; r++)
        t[ty + r*8][tx] = W[(size_t)(k0 + ty + r*8) * N + n0 + tx];
    __syncthreads();
    #pragma unroll
    for (int r = 0; r < 4; r++) {
        float v = t[tx][ty + r*8];
        bf16 h, l; split2(v, h, l);
        const size_t o = (size_t)(n0 + ty + r*8) * K + k0 + tx;
        Th[o] = h; Tl[o] = l;
    }
}

// ------------------------- HMMA split-bf16 GEMM -----------------------------
// OUT: 0 = fp32, 1 = split bf16 (Ch/Cl), 2 = plain bf16 (Cb)
#define TROWB 80
#define TILEB (128*TROWB)
#define STAGEB (4*TILEB)
#define GSMEM (3*STAGEB)

template<int OUT, bool RELU, bool RES>
__global__ __launch_bounds__(256) void hmma_gemm(
    const bf16* __restrict__ Ah, const bf16* __restrict__ Al,
    const bf16* __restrict__ Bh, const bf16* __restrict__ Bl,
    const float* __restrict__ bias, const float* __restrict__ res,
    float* __restrict__ C, bf16* __restrict__ Ch, bf16* __restrict__ Cl,
    bf16* __restrict__ Cb, float alpha, int M, int N, int K)
{
    extern __shared__ char smem[];
    const u32 sbase = smem_u32(smem);

    const int tid = threadIdx.x;
    const int wid = tid >> 5;
    const int lid = tid & 31;
    const int wr  = wid & 1;
    const int wc  = wid >> 1;
    const int bm  = blockIdx.y * 128;
    const int bn  = blockIdx.x * 128;

    const bf16* srcs[4] = {Ah, Al, Bh, Bl};
    const int   rb  [4] = {bm, bm, bn, bn};
    const int nch = K >> 5;

    int l_tile[8], l_seg[8];
    size_t l_grow[8];
    u32 l_sm[8];
    #pragma unroll
    for (int it = 0; it < 8; it++) {
        const int idx = tid + it * 256;
        const int tile = idx >> 9;
        const int r    = (idx >> 2) & 127;
        const int seg  = idx & 3;
        l_tile[it] = tile;
        l_seg[it]  = seg;
        l_grow[it] = (size_t)(rb[tile] + r);
        l_sm[it]   = tile * TILEB + r * TROWB + seg * 16;
    }

    auto load_chunk = [&](int i, int st) {
        const size_t kc = (size_t)i * 32;
        const u32 so = sbase + st * STAGEB;
        #pragma unroll
        for (int it = 0; it < 8; it++) {
            const bf16* gp = srcs[l_tile[it]] + l_grow[it] * (size_t)K + kc + l_seg[it] * 8;
            CP_ASYNC16(so + l_sm[it], gp);
        }
        CP_COMMIT();
    };

    float acc[4][4][4];
    #pragma unroll
    for (int i = 0; i < 4; i++)
        #pragma unroll
        for (int j = 0; j < 4; j++)
            #pragma unroll
            for (int f = 0; f < 4; f++) acc[i][j][f] = 0.f;

    const u32 a_lane = (u32)((wr*64 + (lid & 15)) * TROWB + (lid >> 4) * 16);
    const u32 b_lane = (u32)((wc*32 + (lid & 15)) * TROWB + (lid >> 4) * 16);

    load_chunk(0, 0);
    load_chunk(1, 1);

    for (int i = 0; i < nch; i++) {
        const int st = i % 3;
        if (i + 2 < nch) { load_chunk(i + 2, (i + 2) % 3); CP_WAIT(2); }
        else if (i + 1 < nch) { CP_WAIT(1); }
        else { CP_WAIT(0); }
        __syncthreads();

        const u32 so = sbase + st * STAGEB;
        const u32 aH = so + a_lane;
        const u32 aL = so + TILEB + a_lane;
        const u32 bH = so + 2*TILEB + b_lane;
        const u32 bL = so + 3*TILEB + b_lane;

        #pragma unroll
        for (int ks = 0; ks < 2; ks++) {
            const u32 ko = ks * 32;
            u32 fAh[4][4], fAl[4][4];
            #pragma unroll
            for (int am = 0; am < 4; am++) {
                LDSM_X4(fAh[am][0], fAh[am][1], fAh[am][2], fAh[am][3],
                        aH + am * (16*TROWB) + ko);
                LDSM_X4(fAl[am][0], fAl[am][1], fAl[am][2], fAl[am][3],
                        aL + am * (16*TROWB) + ko);
            }
            u32 fBh[4][2], fBl[4][2];
            #pragma unroll
            for (int bt2 = 0; bt2 < 2; bt2++) {
                u32 r0, r1, r2, r3;
                LDSM_X4(r0, r1, r2, r3, bH + bt2 * (16*TROWB) + ko);
                fBh[bt2*2  ][0] = r0; fBh[bt2*2  ][1] = r2;
                fBh[bt2*2+1][0] = r1; fBh[bt2*2+1][1] = r3;
                LDSM_X4(r0, r1, r2, r3, bL + bt2 * (16*TROWB) + ko);
                fBl[bt2*2  ][0] = r0; fBl[bt2*2  ][1] = r2;
                fBl[bt2*2+1][0] = r1; fBl[bt2*2+1][1] = r3;
            }
            #pragma unroll
            for (int am = 0; am < 4; am++)
                #pragma unroll
                for (int bt = 0; bt < 4; bt++) {
                    MMA_BF16(acc[am][bt], fAh[am], fBh[bt]);
                    MMA_BF16(acc[am][bt], fAh[am], fBl[bt]);
                    MMA_BF16(acc[am][bt], fAl[am], fBh[bt]);
                }
        }
        __syncthreads();
    }

    const int r0 = bm + wr*64 + (lid >> 2);
    const int c0 = bn + wc*32 + (lid & 3) * 2;
    #pragma unroll
    for (int am = 0; am < 4; am++) {
        #pragma unroll
        for (int bt = 0; bt < 4; bt++) {
            const int col = c0 + bt * 8;
            const float2 bv = *(const float2*)(bias + col);
            #pragma unroll
            for (int half = 0; half < 2; half++) {
                const int row = r0 + am*16 + half*8;
                float v0 = (acc[am][bt][half*2 + 0] + bv.x) * alpha;
                float v1 = (acc[am][bt][half*2 + 1] + bv.y) * alpha;
                if (RELU) { v0 = fmaxf(v0, 0.f); v1 = fmaxf(v1, 0.f); }
                if (RES) {
                    const float2 rr = *(const float2*)(res + (size_t)row * N + col);
                    v0 += rr.x; v1 += rr.y;
                }
                if (OUT == 1) {
                    bf16 h0, h1, l0, l1;
                    split2(v0, h0, l0); split2(v1, h1, l1);
                    __nv_bfloat162 hp; hp.x = h0; hp.y = h1;
                    __nv_bfloat162 lp; lp.x = l0; lp.y = l1;
                    *(__nv_bfloat162*)(Ch + (size_t)row * N + col) = hp;
                    *(__nv_bfloat162*)(Cl + (size_t)row * N + col) = lp;
                } else if (OUT == 2) {
                    u32 pk = pack_bf2(v0, v1);
                    *(u32*)(Cb + (size_t)row * N + col) = pk;
                } else {
                    float2 o; o.x = v0; o.y = v1;
                    *(float2*)(C + (size_t)row * N + col) = o;
                }
            }
        }
    }
}

// ------------------------- HMMA flash attention ------------------------------
// Q pre-scaled by 0.125 (GEMM alpha). bf16 Q/K/V. 8 warps x 16 q-rows = 128 q/CTA.
// smem (bf16 row stride 72 elems = 144 B):
//   Q   [128][72]          @ 0       (18432 B)
//   K   2 x [64][72]       @ 18432   (9216 B each)
//   V   2 x [64][72]       @ 36864
//   madd 2 x [64] float    @ 55296   (256 B each)
#define AQ_OFF   0
#define AK_OFF(st) (18432 + (st)*9216)
#define AV_OFF(st) (36864 + (st)*9216)
#define AM_OFF(st) (55296 + (st)*256)
#define ASMEM    55808

__global__ __launch_bounds__(256) void attn_mma_kernel(
    const bf16* __restrict__ Q, const bf16* __restrict__ K,
    const bf16* __restrict__ V, const int* __restrict__ mask,
    bf16* __restrict__ Oh, bf16* __restrict__ Ol)
{
    extern __shared__ char sm[];
    const u32 sb = smem_u32(sm);
    const int tid = threadIdx.x;
    const int wid = tid >> 5;
    const int lid = tid & 31;
    const int h = blockIdx.y;
    const int b = blockIdx.z;
    const size_t qrow0 = (size_t)(b * S_ + blockIdx.x * 128);

    // stage Q tile (128 x 64 bf16)
    for (int t = tid; t < 1024; t += 256) {
        const int r = t >> 3, cseg = t & 7;
        const uint4 v = *(const uint4*)(Q + (qrow0 + r) * D_ + h * 64 + cseg * 8);
        *(uint4*)(sm + AQ_OFF + r * 144 + cseg * 16) = v;
    }
    __syncthreads();

    // Q fragments: [kstep][4]
    u32 qf[4][4];
    const u32 qaddr = sb + AQ_OFF + (u32)((wid * 16 + (lid & 15)) * 144 + (lid >> 4) * 16);
    #pragma unroll
    for (int ks = 0; ks < 4; ks++)
        LDSM_X4(qf[ks][0], qf[ks][1], qf[ks][2], qf[ks][3], qaddr + ks * 32);

    float m0 = -INFINITY, m1 = -INFINITY, l0 = 0.f, l1 = 0.f;
    float o[8][4];
    #pragma unroll
    for (int t = 0; t < 8; t++)
        #pragma unroll
        for (int f = 0; f < 4; f++) o[t][f] = 0.f;

    auto load_kv = [&](int jt, int st) {
        const size_t krow0 = (size_t)(b * S_ + jt * 64);
        #pragma unroll
        for (int it = 0; it < 4; it++) {
            const int t = tid + it * 256;
            const int tile = t >> 9;
            const int r = (t >> 3) & 63;
            const int cseg = t & 7;
            const bf16* src = (tile ? V : K) + (krow0 + r) * D_ + h * 64 + cseg * 8;
            const u32 dst = sb + (tile ? AV_OFF(st) : AK_OFF(st)) + (u32)(r * 144 + cseg * 16);
            CP_ASYNC16(dst, src);
        }
        if (tid < 64) {
            const int mv = mask[b * S_ + jt * 64 + tid];
            *(float*)(sm + AM_OFF(st) + tid * 4) = mv ? 0.f : -1e9f;
        }
        CP_COMMIT();
    };

    load_kv(0, 0);

    const int ntiles = S_ / 64;
    for (int jt = 0; jt < ntiles; jt++) {
        const int st = jt & 1;
        if (jt + 1 < ntiles) { load_kv(jt + 1, st ^ 1); CP_WAIT(1); }
        else { CP_WAIT(0); }
        __syncthreads();

        // ---- S = Q @ K^T ----
        float s[8][4];
        #pragma unroll
        for (int t = 0; t < 8; t++)
            #pragma unroll
            for (int f = 0; f < 4; f++) s[t][f] = 0.f;

        const u32 kaddr = sb + AK_OFF(st) + (u32)(((lid & 15)) * 144 + (lid >> 4) * 16);
        #pragma unroll
        for (int ks = 0; ks < 4; ks++) {
            #pragma unroll
            for (int nt2 = 0; nt2 < 4; nt2++) {
                u32 r0, r1, r2, r3;
                LDSM_X4(r0, r1, r2, r3, kaddr + nt2 * (16*144) + ks * 32);
                u32 bA[2] = {r0, r2};
                u32 bB[2] = {r1, r3};
                MMA_BF16(s[nt2*2],     qf[ks], bA);
                MMA_BF16(s[nt2*2 + 1], qf[ks], bB);
            }
        }

        // ---- mask + online softmax ----
        float mx0 = -INFINITY, mx1 = -INFINITY;
        #pragma unroll
        for (int t = 0; t < 8; t++) {
            const float ma = *(const float*)(sm + AM_OFF(st) + (t*8 + (lid & 3)*2) * 4);
            const float mb = *(const float*)(sm + AM_OFF(st) + (t*8 + (lid & 3)*2 + 1) * 4);
            s[t][0] += ma; s[t][1] += mb; s[t][2] += ma; s[t][3] += mb;
            mx0 = fmaxf(mx0, fmaxf(s[t][0], s[t][1]));
            mx1 = fmaxf(mx1, fmaxf(s[t][2], s[t][3]));
        }
        mx0 = fmaxf(mx0, __shfl_xor_sync(0xffffffffu, mx0, 1));
        mx0 = fmaxf(mx0, __shfl_xor_sync(0xffffffffu, mx0, 2));
        mx1 = fmaxf(mx1, __shfl_xor_sync(0xffffffffu, mx1, 1));
        mx1 = fmaxf(mx1, __shfl_xor_sync(0xffffffffu, mx1, 2));

        const float nm0 = fmaxf(m0, mx0);
        const float nm1 = fmaxf(m1, mx1);
        const float f0 = __expf(m0 - nm0);
        const float f1 = __expf(m1 - nm1);
        m0 = nm0; m1 = nm1;
        l0 *= f0;  l1 *= f1;
        #pragma unroll
        for (int t = 0; t < 8; t++) {
            o[t][0] *= f0; o[t][1] *= f0;
            o[t][2] *= f1; o[t][3] *= f1;
        }

        // ---- P = exp(S - m), pack to A fragments ----
        u32 pa[4][4];
        float ps0 = 0.f, ps1 = 0.f;
        #pragma unroll
        for (int t = 0; t < 8; t++) {
            const float p0 = __expf(s[t][0] - m0);
            const float p1 = __expf(s[t][1] - m0);
            const float p2 = __expf(s[t][2] - m1);
            const float p3 = __expf(s[t][3] - m1);
            ps0 += p0 + p1; ps1 += p2 + p3;
            const u32 lo = pack_bf2(p0, p1);
            const u32 hi = pack_bf2(p2, p3);
            pa[t >> 1][(t & 1) * 2]     = lo;
            pa[t >> 1][(t & 1) * 2 + 1] = hi;
        }
        ps0 += __shfl_xor_sync(0xffffffffu, ps0, 1);
        ps0 += __shfl_xor_sync(0xffffffffu, ps0, 2);
        ps1 += __shfl_xor_sync(0xffffffffu, ps1, 1);
        ps1 += __shfl_xor_sync(0xffffffffu, ps1, 2);
        l0 += ps0; l1 += ps1;

        // ---- O += P @ V ----
        const u32 vaddr = sb + AV_OFF(st) + (u32)(((lid & 15)) * 144 + (lid >> 4) * 16);
        #pragma unroll
        for (int ks = 0; ks < 4; ks++) {
            #pragma unroll
            for (int dt2 = 0; dt2 < 4; dt2++) {
                u32 r0, r1, r2, r3;
                LDSM_X4_T(r0, r1, r2, r3, vaddr + ks * (16*144) + dt2 * 32);
                u32 bA[2] = {r0, r1};
                u32 bB[2] = {r2, r3};
                MMA_BF16(o[dt2*2],     pa[ks], bA);
                MMA_BF16(o[dt2*2 + 1], pa[ks], bB);
            }
        }
        __syncthreads();
    }

    // ---- finalize ----
    const float inv0 = (l0 > 0.f) ? 1.f / l0 : 0.f;
    const float inv1 = (l1 > 0.f) ? 1.f / l1 : 0.f;
    const size_t row0 = qrow0 + wid * 16 + (lid >> 2);
    const int colb = h * 64 + (lid & 3) * 2;
    #pragma unroll
    for (int t = 0; t < 8; t++) {
        const int col = colb + t * 8;
        float v0 = o[t][0] * inv0, v1 = o[t][1] * inv0;
        float v2 = o[t][2] * inv1, v3 = o[t][3] * inv1;
        bf16 h0,h1,l0b,l1b,h2,h3,l2b,l3b;
        split2(v0,h0,l0b); split2(v1,h1,l1b);
        split2(v2,h2,l2b); split2(v3,h3,l3b);
        __nv_bfloat162 hpA; hpA.x=h0; hpA.y=h1;
        __nv_bfloat162 lpA; lpA.x=l0b; lpA.y=l1b;
        __nv_bfloat162 hpB; hpB.x=h2; hpB.y=h3;
        __nv_bfloat162 lpB; lpB.x=l2b; lpB.y=l3b;
        *(__nv_bfloat162*)(Oh + row0 * D_ + col)       = hpA;
        *(__nv_bfloat162*)(Ol + row0 * D_ + col)       = lpA;
        *(__nv_bfloat162*)(Oh + (row0 + 8) * D_ + col) = hpB;
        *(__nv_bfloat162*)(Ol + (row0 + 8) * D_ + col) = lpB;
    }
}

// ------------------------- launch -------------------------------------------
extern "C" void kernel_launch(void* const* d_in, const int* in_sizes, int n_in,
                              void* d_out, int out_size)
{
    const float* x    = (const float*)d_in[0];
    const int*   mask = (const int*)  d_in[1];
    const float* wq   = (const float*)d_in[2];
    const float* bq   = (const float*)d_in[3];
    const float* wk   = (const float*)d_in[4];
    const float* bk   = (const float*)d_in[5];
    const float* wv   = (const float*)d_in[6];
    const float* bv   = (const float*)d_in[7];
    const float* wo   = (const float*)d_in[8];
    const float* bo   = (const float*)d_in[9];
    const float* g1   = (const float*)d_in[10];
    const float* be1  = (const float*)d_in[11];
    const float* g2   = (const float*)d_in[12];
    const float* be2  = (const float*)d_in[13];
    const float* w1   = (const float*)d_in[14];
    const float* bf1  = (const float*)d_in[15];
    const float* w2   = (const float*)d_in[16];
    const float* bf2  = (const float*)d_in[17];
    float* out = (float*)d_out;

    void* p;
    cudaGetSymbolAddress(&p, g_xnh);  bf16* xnh = (bf16*)p;
    cudaGetSymbolAddress(&p, g_xnl);  bf16* xnl = (bf16*)p;
    cudaGetSymbolAddress(&p, g_qb);   bf16* qb  = (bf16*)p;
    cudaGetSymbolAddress(&p, g_kb);   bf16* kb  = (bf16*)p;
    cudaGetSymbolAddress(&p, g_vb);   bf16* vb  = (bf16*)p;
    cudaGetSymbolAddress(&p, g_atth); bf16* ath = (bf16*)p;
    cudaGetSymbolAddress(&p, g_attl); bf16* atl = (bf16*)p;
    cudaGetSymbolAddress(&p, g_x2);   float* x2 = (float*)p;
    cudaGetSymbolAddress(&p, g_hh);   bf16* hh  = (bf16*)p;
    cudaGetSymbolAddress(&p, g_hl);   bf16* hl  = (bf16*)p;
    cudaGetSymbolAddress(&p, g_wqh);  bf16* wqh = (bf16*)p;
    cudaGetSymbolAddress(&p, g_wql);  bf16* wql = (bf16*)p;
    cudaGetSymbolAddress(&p, g_wkh);  bf16* wkh = (bf16*)p;
    cudaGetSymbolAddress(&p, g_wkl);  bf16* wkl = (bf16*)p;
    cudaGetSymbolAddress(&p, g_wvh);  bf16* wvh = (bf16*)p;
    cudaGetSymbolAddress(&p, g_wvl);  bf16* wvl = (bf16*)p;
    cudaGetSymbolAddress(&p, g_woh);  bf16* woh = (bf16*)p;
    cudaGetSymbolAddress(&p, g_wol);  bf16* wol = (bf16*)p;
    cudaGetSymbolAddress(&p, g_w1h);  bf16* w1h = (bf16*)p;
    cudaGetSymbolAddress(&p, g_w1l);  bf16* w1l = (bf16*)p;
    cudaGetSymbolAddress(&p, g_w2h);  bf16* w2h = (bf16*)p;
    cudaGetSymbolAddress(&p, g_w2l);  bf16* w2l = (bf16*)p;

    cudaFuncSetAttribute(hmma_gemm<2,false,false>, cudaFuncAttributeMaxDynamicSharedMemorySize, GSMEM);
    cudaFuncSetAttribute(hmma_gemm<0,false,true >, cudaFuncAttributeMaxDynamicSharedMemorySize, GSMEM);
    cudaFuncSetAttribute(hmma_gemm<1,true ,false>, cudaFuncAttributeMaxDynamicSharedMemorySize, GSMEM);
    cudaFuncSetAttribute(attn_mma_kernel, cudaFuncAttributeMaxDynamicSharedMemorySize, ASMEM);

    const dim3 tb(32, 8);
    tsplit_kernel<<<dim3(D_/32, D_/32), tb>>>(wq, wqh, wql, D_, D_);
    tsplit_kernel<<<dim3(D_/32, D_/32), tb>>>(wk, wkh, wkl, D_, D_);
    tsplit_kernel<<<dim3(D_/32, D_/32), tb>>>(wv, wvh, wvl, D_, D_);
    tsplit_kernel<<<dim3(D_/32, D_/32), tb>>>(wo, woh, wol, D_, D_);
    tsplit_kernel<<<dim3(F_/32, D_/32), tb>>>(w1, w1h, w1l, D_, F_);
    tsplit_kernel<<<dim3(D_/32, F_/32), tb>>>(w2, w2h, w2l, F_, D_);

    ln_split_kernel<<<M_, 256>>>(x, g1, be1, xnh, xnl);

    const dim3 gD(D_/128, M_/128);
    // QKV -> plain bf16 (Q pre-scaled by 1/8)
    hmma_gemm<2,false,false><<<gD, 256, GSMEM>>>(xnh, xnl, wqh, wql, bq, nullptr, nullptr, nullptr, nullptr, qb, 0.125f, M_, D_, D_);
    hmma_gemm<2,false,false><<<gD, 256, GSMEM>>>(xnh, xnl, wkh, wkl, bk, nullptr, nullptr, nullptr, nullptr, kb, 1.0f, M_, D_, D_);
    hmma_gemm<2,false,false><<<gD, 256, GSMEM>>>(xnh, xnl, wvh, wvl, bv, nullptr, nullptr, nullptr, nullptr, vb, 1.0f, M_, D_, D_);

    dim3 attG(S_/128, H_, B_);
    attn_mma_kernel<<<attG, 256, ASMEM>>>(qb, kb, vb, mask, ath, atl);

    hmma_gemm<0,false,true><<<gD, 256, GSMEM>>>(ath, atl, woh, wol, bo, x, x2, nullptr, nullptr, nullptr, 1.0f, M_, D_, D_);

    ln_split_kernel<<<M_, 256>>>(x2, g2, be2, xnh, xnl);

    const dim3 gF(F_/128, M_/128);
    hmma_gemm<1,true,false><<<gF, 256, GSMEM>>>(xnh, xnl, w1h, w1l, bf1, nullptr, nullptr, hh, hl, nullptr, 1.0f, M_, F_, D_);

    hmma_gemm<0,false,true><<<gD, 256, GSMEM>>>(hh, hl, w2h, w2l, bf2, x2, out, nullptr, nullptr, nullptr, 1.0f, M_, D_, F_);
}

// round 5
// speedup vs baseline: 3.0820x; 1.0761x over previous
#include <cuda_runtime.h>
#include <cuda_bf16.h>
#include <math.h>

typedef unsigned int u32;
typedef unsigned long long u64;
using bf16 = __nv_bfloat16;

#define B_   2
#define S_   2048
#define D_   1024
#define H_   16
#define F_   4096
#define M_   (B_*S_)
#define QKVN 3072

// ------------------------- scratch (device globals) -------------------------
__device__ __align__(16) bf16  g_xnh[M_*D_],  g_xnl[M_*D_];
__device__ __align__(16) bf16  g_qkv[(size_t)M_*QKVN];
__device__ __align__(16) bf16  g_atth[M_*D_], g_attl[M_*D_];
__device__ __align__(16) float g_x2[M_*D_];
__device__ __align__(16) bf16  g_hh[(size_t)M_*F_], g_hl[(size_t)M_*F_];
__device__ __align__(16) bf16  g_wqkvh[(size_t)QKVN*D_], g_wqkvl[(size_t)QKVN*D_];
__device__ __align__(16) float g_bqkv[QKVN];
__device__ __align__(16) bf16  g_woh[D_*D_], g_wol[D_*D_];
__device__ __align__(16) bf16  g_w1h[(size_t)F_*D_], g_w1l[(size_t)F_*D_];
__device__ __align__(16) bf16  g_w2h[(size_t)D_*F_], g_w2l[(size_t)D_*F_];

// ------------------------- helpers ------------------------------------------
__device__ __forceinline__ u32 smem_u32(const void* p) {
    u32 a;
    asm("{ .reg .u64 t; cvta.to.shared.u64 t, %1; cvt.u32.u64 %0, t; }"
        : "=r"(a) : "l"(p));
    return a;
}
#define CP_ASYNC16(sm, gp) \
    asm volatile("cp.async.cg.shared.global [%0], [%1], 16;" :: "r"(sm), "l"(gp))
#define CP_COMMIT() asm volatile("cp.async.commit_group;" ::: "memory")
#define CP_WAIT(n)  asm volatile("cp.async.wait_group %0;" :: "n"(n) : "memory")

#define LDSM_X4(r0,r1,r2,r3,a) \
    asm volatile("ldmatrix.sync.aligned.m8n8.x4.shared.b16 {%0,%1,%2,%3}, [%4];" \
        : "=r"(r0), "=r"(r1), "=r"(r2), "=r"(r3) : "r"(a))
#define LDSM_X4_T(r0,r1,r2,r3,a) \
    asm volatile("ldmatrix.sync.aligned.m8n8.x4.trans.shared.b16 {%0,%1,%2,%3}, [%4];" \
        : "=r"(r0), "=r"(r1), "=r"(r2), "=r"(r3) : "r"(a))

#define MMA_BF16(d, a, b) \
    asm volatile("mma.sync.aligned.m16n8k16.row.col.f32.bf16.bf16.f32 " \
        "{%0,%1,%2,%3}, {%4,%5,%6,%7}, {%8,%9}, {%0,%1,%2,%3};" \
        : "+f"((d)[0]), "+f"((d)[1]), "+f"((d)[2]), "+f"((d)[3]) \
        : "r"((a)[0]), "r"((a)[1]), "r"((a)[2]), "r"((a)[3]), \
          "r"((b)[0]), "r"((b)[1]))

__device__ __forceinline__ void split2(float v, bf16& h, bf16& l) {
    h = __float2bfloat16_rn(v);
    l = __float2bfloat16_rn(v - __bfloat162float(h));
}
__device__ __forceinline__ u32 pack_bf2(float a, float b) {
    __nv_bfloat162 t = __float22bfloat162_rn(make_float2(a, b));
    return *(u32*)&t;
}

// ------------------------- layernorm with split output ----------------------
__global__ __launch_bounds__(256) void ln_split_kernel(
    const float* __restrict__ x, const float* __restrict__ g,
    const float* __restrict__ b, bf16* __restrict__ oh, bf16* __restrict__ ol)
{
    __shared__ float red[8];
    const int row = blockIdx.x;
    const int tid = threadIdx.x;
    const float* xr = x + (size_t)row * D_;

    float4 xv = *(const float4*)(xr + tid * 4);
    float s = xv.x + xv.y + xv.z + xv.w;
    #pragma unroll
    for (int o = 16; o > 0; o >>= 1) s += __shfl_xor_sync(0xffffffffu, s, o);
    if ((tid & 31) == 0) red[tid >> 5] = s;
    __syncthreads();
    float tot = 0.f;
    #pragma unroll
    for (int w = 0; w < 8; w++) tot += red[w];
    const float mean = tot * (1.0f / D_);

    float d0 = xv.x - mean, d1 = xv.y - mean, d2 = xv.z - mean, d3 = xv.w - mean;
    float sq = d0*d0 + d1*d1 + d2*d2 + d3*d3;
    __syncthreads();
    #pragma unroll
    for (int o = 16; o > 0; o >>= 1) sq += __shfl_xor_sync(0xffffffffu, sq, o);
    if ((tid & 31) == 0) red[tid >> 5] = sq;
    __syncthreads();
    float vtot = 0.f;
    #pragma unroll
    for (int w = 0; w < 8; w++) vtot += red[w];
    const float rstd = rsqrtf(vtot * (1.0f / D_) + 1e-5f);

    float4 gv = *(const float4*)(g + tid * 4);
    float4 bv = *(const float4*)(b + tid * 4);
    float o0 = d0 * rstd * gv.x + bv.x;
    float o1 = d1 * rstd * gv.y + bv.y;
    float o2 = d2 * rstd * gv.z + bv.z;
    float o3 = d3 * rstd * gv.w + bv.w;

    bf16 h0,h1,h2,h3,l0,l1,l2,l3;
    split2(o0,h0,l0); split2(o1,h1,l1); split2(o2,h2,l2); split2(o3,h3,l3);
    const size_t off = (size_t)row * D_ + tid * 4;
    __nv_bfloat162 hp0; hp0.x=h0; hp0.y=h1;
    __nv_bfloat162 hp1; hp1.x=h2; hp1.y=h3;
    __nv_bfloat162 lp0; lp0.x=l0; lp0.y=l1;
    __nv_bfloat162 lp1; lp1.x=l2; lp1.y=l3;
    *(__nv_bfloat162*)(oh + off)     = hp0;
    *(__nv_bfloat162*)(oh + off + 2) = hp1;
    *(__nv_bfloat162*)(ol + off)     = lp0;
    *(__nv_bfloat162*)(ol + off + 2) = lp1;
}

// ------------------------- weight transpose + split -------------------------
__global__ __launch_bounds__(256) void tsplit_kernel(
    const float* __restrict__ W, bf16* __restrict__ Th, bf16* __restrict__ Tl,
    int K, int N)
{
    __shared__ float t[32][33];
    const int tx = threadIdx.x, ty = threadIdx.y;
    const int n0 = blockIdx.x * 32, k0 = blockIdx.y * 32;
    #pragma unroll
    for (int r = 0; r < 4; r++)
        t[ty + r*8][tx] = W[(size_t)(k0 + ty + r*8) * N + n0 + tx];
    __syncthreads();
    #pragma unroll
    for (int r = 0; r < 4; r++) {
        float v = t[tx][ty + r*8];
        bf16 h, l; split2(v, h, l);
        const size_t o = (size_t)(n0 + ty + r*8) * K + k0 + tx;
        Th[o] = h; Tl[o] = l;
    }
}

__global__ void pack_bias_kernel(const float* __restrict__ bq,
                                 const float* __restrict__ bk,
                                 const float* __restrict__ bv,
                                 float* __restrict__ o)
{
    const int i = blockIdx.x * 256 + threadIdx.x;
    if (i < 1024)       o[i] = bq[i];
    else if (i < 2048)  o[i] = bk[i - 1024];
    else                o[i] = bv[i - 2048];
}

// ------------------------- HMMA split-bf16 GEMM -----------------------------
// OUT: 0 = fp32, 1 = split bf16 (Ch/Cl), 2 = plain bf16 (Cb)
// QKVA: per-column alpha (0.125 for cols < 1024) for the fused QKV GEMM.
#define TROWB 80
#define TILEB (128*TROWB)
#define STAGEB (4*TILEB)
#define GSMEM (2*STAGEB)

template<int OUT, bool RELU, bool RES, bool QKVA>
__global__ __launch_bounds__(256, 2) void hmma_gemm(
    const bf16* __restrict__ Ah, const bf16* __restrict__ Al,
    const bf16* __restrict__ Bh, const bf16* __restrict__ Bl,
    const float* __restrict__ bias, const float* __restrict__ res,
    float* __restrict__ C, bf16* __restrict__ Ch, bf16* __restrict__ Cl,
    bf16* __restrict__ Cb, int M, int N, int K)
{
    extern __shared__ char smem[];
    const u32 sbase = smem_u32(smem);

    const int tid = threadIdx.x;
    const int wid = tid >> 5;
    const int lid = tid & 31;
    const int wr  = wid & 1;
    const int wc  = wid >> 1;
    const int bm  = blockIdx.y * 128;
    const int bn  = blockIdx.x * 128;

    const bf16* srcs[4] = {Ah, Al, Bh, Bl};
    const int   rb  [4] = {bm, bm, bn, bn};
    const int nch = K >> 5;

    int l_tile[8], l_seg[8];
    size_t l_grow[8];
    u32 l_sm[8];
    #pragma unroll
    for (int it = 0; it < 8; it++) {
        const int idx = tid + it * 256;
        const int tile = idx >> 9;
        const int r    = (idx >> 2) & 127;
        const int seg  = idx & 3;
        l_tile[it] = tile;
        l_seg[it]  = seg;
        l_grow[it] = (size_t)(rb[tile] + r);
        l_sm[it]   = tile * TILEB + r * TROWB + seg * 16;
    }

    auto load_chunk = [&](int i, int st) {
        const size_t kc = (size_t)i * 32;
        const u32 so = sbase + st * STAGEB;
        #pragma unroll
        for (int it = 0; it < 8; it++) {
            const bf16* gp = srcs[l_tile[it]] + l_grow[it] * (size_t)K + kc + l_seg[it] * 8;
            CP_ASYNC16(so + l_sm[it], gp);
        }
        CP_COMMIT();
    };

    float acc[4][4][4];
    #pragma unroll
    for (int i = 0; i < 4; i++)
        #pragma unroll
        for (int j = 0; j < 4; j++)
            #pragma unroll
            for (int f = 0; f < 4; f++) acc[i][j][f] = 0.f;

    const u32 a_lane = (u32)((wr*64 + (lid & 15)) * TROWB + (lid >> 4) * 16);
    const u32 b_lane = (u32)((wc*32 + (lid & 15)) * TROWB + (lid >> 4) * 16);

    load_chunk(0, 0);

    for (int i = 0; i < nch; i++) {
        const int st = i & 1;
        if (i + 1 < nch) { load_chunk(i + 1, st ^ 1); CP_WAIT(1); }
        else { CP_WAIT(0); }
        __syncthreads();

        const u32 so = sbase + st * STAGEB;
        const u32 aH = so + a_lane;
        const u32 aL = so + TILEB + a_lane;
        const u32 bH = so + 2*TILEB + b_lane;
        const u32 bL = so + 3*TILEB + b_lane;

        #pragma unroll
        for (int ks = 0; ks < 2; ks++) {
            const u32 ko = ks * 32;
            u32 fAh[4][4], fAl[4][4];
            #pragma unroll
            for (int am = 0; am < 4; am++) {
                LDSM_X4(fAh[am][0], fAh[am][1], fAh[am][2], fAh[am][3],
                        aH + am * (16*TROWB) + ko);
                LDSM_X4(fAl[am][0], fAl[am][1], fAl[am][2], fAl[am][3],
                        aL + am * (16*TROWB) + ko);
            }
            u32 fBh[4][2], fBl[4][2];
            #pragma unroll
            for (int bt2 = 0; bt2 < 2; bt2++) {
                u32 r0, r1, r2, r3;
                LDSM_X4(r0, r1, r2, r3, bH + bt2 * (16*TROWB) + ko);
                fBh[bt2*2  ][0] = r0; fBh[bt2*2  ][1] = r2;
                fBh[bt2*2+1][0] = r1; fBh[bt2*2+1][1] = r3;
                LDSM_X4(r0, r1, r2, r3, bL + bt2 * (16*TROWB) + ko);
                fBl[bt2*2  ][0] = r0; fBl[bt2*2  ][1] = r2;
                fBl[bt2*2+1][0] = r1; fBl[bt2*2+1][1] = r3;
            }
            #pragma unroll
            for (int am = 0; am < 4; am++)
                #pragma unroll
                for (int bt = 0; bt < 4; bt++) {
                    MMA_BF16(acc[am][bt], fAh[am], fBh[bt]);
                    MMA_BF16(acc[am][bt], fAh[am], fBl[bt]);
                    MMA_BF16(acc[am][bt], fAl[am], fBh[bt]);
                }
        }
        __syncthreads();
    }

    const int r0 = bm + wr*64 + (lid >> 2);
    const int c0 = bn + wc*32 + (lid & 3) * 2;
    #pragma unroll
    for (int am = 0; am < 4; am++) {
        #pragma unroll
        for (int bt = 0; bt < 4; bt++) {
            const int col = c0 + bt * 8;
            const float2 bv = *(const float2*)(bias + col);
            const float alpha = QKVA ? ((col < 1024) ? 0.125f : 1.0f) : 1.0f;
            #pragma unroll
            for (int half = 0; half < 2; half++) {
                const int row = r0 + am*16 + half*8;
                float v0 = (acc[am][bt][half*2 + 0] + bv.x) * alpha;
                float v1 = (acc[am][bt][half*2 + 1] + bv.y) * alpha;
                if (RELU) { v0 = fmaxf(v0, 0.f); v1 = fmaxf(v1, 0.f); }
                if (RES) {
                    const float2 rr = *(const float2*)(res + (size_t)row * N + col);
                    v0 += rr.x; v1 += rr.y;
                }
                if (OUT == 1) {
                    bf16 h0, h1, l0, l1;
                    split2(v0, h0, l0); split2(v1, h1, l1);
                    __nv_bfloat162 hp; hp.x = h0; hp.y = h1;
                    __nv_bfloat162 lp; lp.x = l0; lp.y = l1;
                    *(__nv_bfloat162*)(Ch + (size_t)row * N + col) = hp;
                    *(__nv_bfloat162*)(Cl + (size_t)row * N + col) = lp;
                } else if (OUT == 2) {
                    u32 pk = pack_bf2(v0, v1);
                    *(u32*)(Cb + (size_t)row * N + col) = pk;
                } else {
                    float2 o; o.x = v0; o.y = v1;
                    *(float2*)(C + (size_t)row * N + col) = o;
                }
            }
        }
    }
}

// ------------------------- HMMA flash attention ------------------------------
// Q/K/V are column slices of the packed QKV buffer (row stride QKVN).
#define AQ_OFF   0
#define AK_OFF(st) (18432 + (st)*9216)
#define AV_OFF(st) (36864 + (st)*9216)
#define AM_OFF(st) (55296 + (st)*256)
#define ASMEM    55808

__global__ __launch_bounds__(256) void attn_mma_kernel(
    const bf16* __restrict__ QKV, const int* __restrict__ mask,
    bf16* __restrict__ Oh, bf16* __restrict__ Ol)
{
    extern __shared__ char sm[];
    const u32 sb = smem_u32(sm);
    const int tid = threadIdx.x;
    const int wid = tid >> 5;
    const int lid = tid & 31;
    const int h = blockIdx.y;
    const int b = blockIdx.z;
    const size_t qrow0 = (size_t)(b * S_ + blockIdx.x * 128);

    const bf16* Q = QKV;                // cols [0,1024)
    const bf16* K = QKV + 1024;         // cols [1024,2048)
    const bf16* V = QKV + 2048;         // cols [2048,3072)

    // stage Q tile (128 x 64 bf16)
    for (int t = tid; t < 1024; t += 256) {
        const int r = t >> 3, cseg = t & 7;
        const uint4 v = *(const uint4*)(Q + (qrow0 + r) * QKVN + h * 64 + cseg * 8);
        *(uint4*)(sm + AQ_OFF + r * 144 + cseg * 16) = v;
    }
    __syncthreads();

    u32 qf[4][4];
    const u32 qaddr = sb + AQ_OFF + (u32)((wid * 16 + (lid & 15)) * 144 + (lid >> 4) * 16);
    #pragma unroll
    for (int ks = 0; ks < 4; ks++)
        LDSM_X4(qf[ks][0], qf[ks][1], qf[ks][2], qf[ks][3], qaddr + ks * 32);

    float m0 = -INFINITY, m1 = -INFINITY, l0 = 0.f, l1 = 0.f;
    float o[8][4];
    #pragma unroll
    for (int t = 0; t < 8; t++)
        #pragma unroll
        for (int f = 0; f < 4; f++) o[t][f] = 0.f;

    auto load_kv = [&](int jt, int st) {
        const size_t krow0 = (size_t)(b * S_ + jt * 64);
        #pragma unroll
        for (int it = 0; it < 4; it++) {
            const int t = tid + it * 256;
            const int tile = t >> 9;
            const int r = (t >> 3) & 63;
            const int cseg = t & 7;
            const bf16* src = (tile ? V : K) + (krow0 + r) * QKVN + h * 64 + cseg * 8;
            const u32 dst = sb + (tile ? AV_OFF(st) : AK_OFF(st)) + (u32)(r * 144 + cseg * 16);
            CP_ASYNC16(dst, src);
        }
        if (tid < 64) {
            const int mv = mask[b * S_ + jt * 64 + tid];
            *(float*)(sm + AM_OFF(st) + tid * 4) = mv ? 0.f : -1e9f;
        }
        CP_COMMIT();
    };

    load_kv(0, 0);

    const int ntiles = S_ / 64;
    for (int jt = 0; jt < ntiles; jt++) {
        const int st = jt & 1;
        if (jt + 1 < ntiles) { load_kv(jt + 1, st ^ 1); CP_WAIT(1); }
        else { CP_WAIT(0); }
        __syncthreads();

        float s[8][4];
        #pragma unroll
        for (int t = 0; t < 8; t++)
            #pragma unroll
            for (int f = 0; f < 4; f++) s[t][f] = 0.f;

        const u32 kaddr = sb + AK_OFF(st) + (u32)(((lid & 15)) * 144 + (lid >> 4) * 16);
        #pragma unroll
        for (int ks = 0; ks < 4; ks++) {
            #pragma unroll
            for (int nt2 = 0; nt2 < 4; nt2++) {
                u32 r0, r1, r2, r3;
                LDSM_X4(r0, r1, r2, r3, kaddr + nt2 * (16*144) + ks * 32);
                u32 bA[2] = {r0, r2};
                u32 bB[2] = {r1, r3};
                MMA_BF16(s[nt2*2],     qf[ks], bA);
                MMA_BF16(s[nt2*2 + 1], qf[ks], bB);
            }
        }

        float mx0 = -INFINITY, mx1 = -INFINITY;
        #pragma unroll
        for (int t = 0; t < 8; t++) {
            const float ma = *(const float*)(sm + AM_OFF(st) + (t*8 + (lid & 3)*2) * 4);
            const float mb = *(const float*)(sm + AM_OFF(st) + (t*8 + (lid & 3)*2 + 1) * 4);
            s[t][0] += ma; s[t][1] += mb; s[t][2] += ma; s[t][3] += mb;
            mx0 = fmaxf(mx0, fmaxf(s[t][0], s[t][1]));
            mx1 = fmaxf(mx1, fmaxf(s[t][2], s[t][3]));
        }
        mx0 = fmaxf(mx0, __shfl_xor_sync(0xffffffffu, mx0, 1));
        mx0 = fmaxf(mx0, __shfl_xor_sync(0xffffffffu, mx0, 2));
        mx1 = fmaxf(mx1, __shfl_xor_sync(0xffffffffu, mx1, 1));
        mx1 = fmaxf(mx1, __shfl_xor_sync(0xffffffffu, mx1, 2));

        const float nm0 = fmaxf(m0, mx0);
        const float nm1 = fmaxf(m1, mx1);
        const float f0 = __expf(m0 - nm0);
        const float f1 = __expf(m1 - nm1);
        m0 = nm0; m1 = nm1;
        l0 *= f0;  l1 *= f1;
        #pragma unroll
        for (int t = 0; t < 8; t++) {
            o[t][0] *= f0; o[t][1] *= f0;
            o[t][2] *= f1; o[t][3] *= f1;
        }

        u32 pa[4][4];
        float ps0 = 0.f, ps1 = 0.f;
        #pragma unroll
        for (int t = 0; t < 8; t++) {
            const float p0 = __expf(s[t][0] - m0);
            const float p1 = __expf(s[t][1] - m0);
            const float p2 = __expf(s[t][2] - m1);
            const float p3 = __expf(s[t][3] - m1);
            ps0 += p0 + p1; ps1 += p2 + p3;
            const u32 lo = pack_bf2(p0, p1);
            const u32 hi = pack_bf2(p2, p3);
            pa[t >> 1][(t & 1) * 2]     = lo;
            pa[t >> 1][(t & 1) * 2 + 1] = hi;
        }
        ps0 += __shfl_xor_sync(0xffffffffu, ps0, 1);
        ps0 += __shfl_xor_sync(0xffffffffu, ps0, 2);
        ps1 += __shfl_xor_sync(0xffffffffu, ps1, 1);
        ps1 += __shfl_xor_sync(0xffffffffu, ps1, 2);
        l0 += ps0; l1 += ps1;

        const u32 vaddr = sb + AV_OFF(st) + (u32)(((lid & 15)) * 144 + (lid >> 4) * 16);
        #pragma unroll
        for (int ks = 0; ks < 4; ks++) {
            #pragma unroll
            for (int dt2 = 0; dt2 < 4; dt2++) {
                u32 r0, r1, r2, r3;
                LDSM_X4_T(r0, r1, r2, r3, vaddr + ks * (16*144) + dt2 * 32);
                u32 bA[2] = {r0, r1};
                u32 bB[2] = {r2, r3};
                MMA_BF16(o[dt2*2],     pa[ks], bA);
                MMA_BF16(o[dt2*2 + 1], pa[ks], bB);
            }
        }
        __syncthreads();
    }

    const float inv0 = (l0 > 0.f) ? 1.f / l0 : 0.f;
    const float inv1 = (l1 > 0.f) ? 1.f / l1 : 0.f;
    const size_t row0 = qrow0 + wid * 16 + (lid >> 2);
    const int colb = h * 64 + (lid & 3) * 2;
    #pragma unroll
    for (int t = 0; t < 8; t++) {
        const int col = colb + t * 8;
        float v0 = o[t][0] * inv0, v1 = o[t][1] * inv0;
        float v2 = o[t][2] * inv1, v3 = o[t][3] * inv1;
        bf16 h0,h1,l0b,l1b,h2,h3,l2b,l3b;
        split2(v0,h0,l0b); split2(v1,h1,l1b);
        split2(v2,h2,l2b); split2(v3,h3,l3b);
        __nv_bfloat162 hpA; hpA.x=h0; hpA.y=h1;
        __nv_bfloat162 lpA; lpA.x=l0b; lpA.y=l1b;
        __nv_bfloat162 hpB; hpB.x=h2; hpB.y=h3;
        __nv_bfloat162 lpB; lpB.x=l2b; lpB.y=l3b;
        *(__nv_bfloat162*)(Oh + row0 * D_ + col)       = hpA;
        *(__nv_bfloat162*)(Ol + row0 * D_ + col)       = lpA;
        *(__nv_bfloat162*)(Oh + (row0 + 8) * D_ + col) = hpB;
        *(__nv_bfloat162*)(Ol + (row0 + 8) * D_ + col) = lpB;
    }
}

// ------------------------- launch -------------------------------------------
extern "C" void kernel_launch(void* const* d_in, const int* in_sizes, int n_in,
                              void* d_out, int out_size)
{
    const float* x    = (const float*)d_in[0];
    const int*   mask = (const int*)  d_in[1];
    const float* wq   = (const float*)d_in[2];
    const float* bq   = (const float*)d_in[3];
    const float* wk   = (const float*)d_in[4];
    const float* bk   = (const float*)d_in[5];
    const float* wv   = (const float*)d_in[6];
    const float* bv   = (const float*)d_in[7];
    const float* wo   = (const float*)d_in[8];
    const float* bo   = (const float*)d_in[9];
    const float* g1   = (const float*)d_in[10];
    const float* be1  = (const float*)d_in[11];
    const float* g2   = (const float*)d_in[12];
    const float* be2  = (const float*)d_in[13];
    const float* w1   = (const float*)d_in[14];
    const float* bf1  = (const float*)d_in[15];
    const float* w2   = (const float*)d_in[16];
    const float* bf2  = (const float*)d_in[17];
    float* out = (float*)d_out;

    void* p;
    cudaGetSymbolAddress(&p, g_xnh);   bf16* xnh   = (bf16*)p;
    cudaGetSymbolAddress(&p, g_xnl);   bf16* xnl   = (bf16*)p;
    cudaGetSymbolAddress(&p, g_qkv);   bf16* qkv   = (bf16*)p;
    cudaGetSymbolAddress(&p, g_atth);  bf16* ath   = (bf16*)p;
    cudaGetSymbolAddress(&p, g_attl);  bf16* atl   = (bf16*)p;
    cudaGetSymbolAddress(&p, g_x2);    float* x2   = (float*)p;
    cudaGetSymbolAddress(&p, g_hh);    bf16* hh    = (bf16*)p;
    cudaGetSymbolAddress(&p, g_hl);    bf16* hl    = (bf16*)p;
    cudaGetSymbolAddress(&p, g_wqkvh); bf16* wqkvh = (bf16*)p;
    cudaGetSymbolAddress(&p, g_wqkvl); bf16* wqkvl = (bf16*)p;
    cudaGetSymbolAddress(&p, g_bqkv);  float* bqkv = (float*)p;
    cudaGetSymbolAddress(&p, g_woh);   bf16* woh   = (bf16*)p;
    cudaGetSymbolAddress(&p, g_wol);   bf16* wol   = (bf16*)p;
    cudaGetSymbolAddress(&p, g_w1h);   bf16* w1h   = (bf16*)p;
    cudaGetSymbolAddress(&p, g_w1l);   bf16* w1l   = (bf16*)p;
    cudaGetSymbolAddress(&p, g_w2h);   bf16* w2h   = (bf16*)p;
    cudaGetSymbolAddress(&p, g_w2l);   bf16* w2l   = (bf16*)p;

    cudaFuncSetAttribute(hmma_gemm<2,false,false,true >, cudaFuncAttributeMaxDynamicSharedMemorySize, GSMEM);
    cudaFuncSetAttribute(hmma_gemm<0,false,true ,false>, cudaFuncAttributeMaxDynamicSharedMemorySize, GSMEM);
    cudaFuncSetAttribute(hmma_gemm<1,true ,false,false>, cudaFuncAttributeMaxDynamicSharedMemorySize, GSMEM);
    cudaFuncSetAttribute(attn_mma_kernel, cudaFuncAttributeMaxDynamicSharedMemorySize, ASMEM);

    const dim3 tb(32, 8);
    // packed QKV weights: rows [0,1024)=wq^T, [1024,2048)=wk^T, [2048,3072)=wv^T
    tsplit_kernel<<<dim3(D_/32, D_/32), tb>>>(wq, wqkvh,               wqkvl,               D_, D_);
    tsplit_kernel<<<dim3(D_/32, D_/32), tb>>>(wk, wqkvh + 1024*D_,     wqkvl + 1024*D_,     D_, D_);
    tsplit_kernel<<<dim3(D_/32, D_/32), tb>>>(wv, wqkvh + 2048*D_,     wqkvl + 2048*D_,     D_, D_);
    tsplit_kernel<<<dim3(D_/32, D_/32), tb>>>(wo, woh, wol, D_, D_);
    tsplit_kernel<<<dim3(F_/32, D_/32), tb>>>(w1, w1h, w1l, D_, F_);
    tsplit_kernel<<<dim3(D_/32, F_/32), tb>>>(w2, w2h, w2l, F_, D_);
    pack_bias_kernel<<<QKVN/256, 256>>>(bq, bk, bv, bqkv);

    ln_split_kernel<<<M_, 256>>>(x, g1, be1, xnh, xnl);

    // fused QKV GEMM -> packed bf16 [M, 3072] (Q cols pre-scaled by 1/8)
    const dim3 gQKV(QKVN/128, M_/128);
    hmma_gemm<2,false,false,true><<<gQKV, 256, GSMEM>>>(xnh, xnl, wqkvh, wqkvl, bqkv, nullptr, nullptr, nullptr, nullptr, qkv, M_, QKVN, D_);

    dim3 attG(S_/128, H_, B_);
    attn_mma_kernel<<<attG, 256, ASMEM>>>(qkv, mask, ath, atl);

    const dim3 gD(D_/128, M_/128);
    hmma_gemm<0,false,true,false><<<gD, 256, GSMEM>>>(ath, atl, woh, wol, bo, x, x2, nullptr, nullptr, nullptr, M_, D_, D_);

    ln_split_kernel<<<M_, 256>>>(x2, g2, be2, xnh, xnl);

    const dim3 gF(F_/128, M_/128);
    hmma_gemm<1,true,false,false><<<gF, 256, GSMEM>>>(xnh, xnl, w1h, w1l, bf1, nullptr, nullptr, hh, hl, nullptr, M_, F_, D_);

    hmma_gemm<0,false,true,false><<<gD, 256, GSMEM>>>(hh, hl, w2h, w2l, bf2, x2, out, nullptr, nullptr, nullptr, M_, D_, F_);
}

// round 6
// speedup vs baseline: 4.5216x; 1.4671x over previous
#include <cuda_runtime.h>
#include <cuda_bf16.h>
#include <math.h>

typedef unsigned int u32;
typedef unsigned long long u64;
using bf16 = __nv_bfloat16;

#define B_   2
#define S_   2048
#define D_   1024
#define H_   16
#define F_   4096
#define M_   (B_*S_)
#define QKVN 3072

// ------------------------- scratch (device globals) -------------------------
__device__ __align__(16) float g_xn[M_*D_];                 // LN out (tf32-rounded)
__device__ __align__(16) bf16  g_qkv[(size_t)M_*QKVN];      // packed QKV bf16
__device__ __align__(16) float g_att[M_*D_];                // attn out (tf32-rounded)
__device__ __align__(16) float g_x2[M_*D_];                 // residual (exact fp32)
__device__ __align__(16) float g_h[(size_t)M_*F_];          // FFN hidden (tf32-rounded)
__device__ __align__(16) float g_wqkvT[(size_t)QKVN*D_];    // transposed tf32 weights
__device__ __align__(16) float g_bqkv[QKVN];
__device__ __align__(16) float g_woT[D_*D_];
__device__ __align__(16) float g_w1T[(size_t)F_*D_];
__device__ __align__(16) float g_w2T[(size_t)D_*F_];

// ------------------------- helpers ------------------------------------------
__device__ __forceinline__ u32 smem_u32(const void* p) {
    u32 a;
    asm("{ .reg .u64 t; cvta.to.shared.u64 t, %1; cvt.u32.u64 %0, t; }"
        : "=r"(a) : "l"(p));
    return a;
}
#define CP_ASYNC16(sm, gp) \
    asm volatile("cp.async.cg.shared.global [%0], [%1], 16;" :: "r"(sm), "l"(gp))
#define CP_COMMIT() asm volatile("cp.async.commit_group;" ::: "memory")
#define CP_WAIT(n)  asm volatile("cp.async.wait_group %0;" :: "n"(n) : "memory")

#define LDS32(d, a) \
    asm volatile("ld.shared.b32 %0, [%1];" : "=r"(d) : "r"(a))

#define LDSM_X4(r0,r1,r2,r3,a) \
    asm volatile("ldmatrix.sync.aligned.m8n8.x4.shared.b16 {%0,%1,%2,%3}, [%4];" \
        : "=r"(r0), "=r"(r1), "=r"(r2), "=r"(r3) : "r"(a))
#define LDSM_X4_T(r0,r1,r2,r3,a) \
    asm volatile("ldmatrix.sync.aligned.m8n8.x4.trans.shared.b16 {%0,%1,%2,%3}, [%4];" \
        : "=r"(r0), "=r"(r1), "=r"(r2), "=r"(r3) : "r"(a))

#define MMA_BF16(d, a, b) \
    asm volatile("mma.sync.aligned.m16n8k16.row.col.f32.bf16.bf16.f32 " \
        "{%0,%1,%2,%3}, {%4,%5,%6,%7}, {%8,%9}, {%0,%1,%2,%3};" \
        : "+f"((d)[0]), "+f"((d)[1]), "+f"((d)[2]), "+f"((d)[3]) \
        : "r"((a)[0]), "r"((a)[1]), "r"((a)[2]), "r"((a)[3]), \
          "r"((b)[0]), "r"((b)[1]))

#define MMA_TF32(d, a, b) \
    asm volatile("mma.sync.aligned.m16n8k8.row.col.f32.tf32.tf32.f32 " \
        "{%0,%1,%2,%3}, {%4,%5,%6,%7}, {%8,%9}, {%0,%1,%2,%3};" \
        : "+f"((d)[0]), "+f"((d)[1]), "+f"((d)[2]), "+f"((d)[3]) \
        : "r"((a)[0]), "r"((a)[1]), "r"((a)[2]), "r"((a)[3]), \
          "r"((b)[0]), "r"((b)[1]))

__device__ __forceinline__ float tf32r(float v) {
    u32 t;
    asm("cvt.rna.tf32.f32 %0, %1;" : "=r"(t) : "f"(v));
    return __uint_as_float(t);
}
__device__ __forceinline__ u32 pack_bf2(float a, float b) {
    __nv_bfloat162 t = __float22bfloat162_rn(make_float2(a, b));
    return *(u32*)&t;
}

// ------------------------- layernorm (tf32-rounded fp32 out) -----------------
__global__ __launch_bounds__(256) void ln_kernel(
    const float* __restrict__ x, const float* __restrict__ g,
    const float* __restrict__ b, float* __restrict__ o)
{
    __shared__ float red[8];
    const int row = blockIdx.x;
    const int tid = threadIdx.x;
    const float* xr = x + (size_t)row * D_;

    float4 xv = *(const float4*)(xr + tid * 4);
    float s = xv.x + xv.y + xv.z + xv.w;
    #pragma unroll
    for (int of = 16; of > 0; of >>= 1) s += __shfl_xor_sync(0xffffffffu, s, of);
    if ((tid & 31) == 0) red[tid >> 5] = s;
    __syncthreads();
    float tot = 0.f;
    #pragma unroll
    for (int w = 0; w < 8; w++) tot += red[w];
    const float mean = tot * (1.0f / D_);

    float d0 = xv.x - mean, d1 = xv.y - mean, d2 = xv.z - mean, d3 = xv.w - mean;
    float sq = d0*d0 + d1*d1 + d2*d2 + d3*d3;
    __syncthreads();
    #pragma unroll
    for (int of = 16; of > 0; of >>= 1) sq += __shfl_xor_sync(0xffffffffu, sq, of);
    if ((tid & 31) == 0) red[tid >> 5] = sq;
    __syncthreads();
    float vtot = 0.f;
    #pragma unroll
    for (int w = 0; w < 8; w++) vtot += red[w];
    const float rstd = rsqrtf(vtot * (1.0f / D_) + 1e-5f);

    float4 gv = *(const float4*)(g + tid * 4);
    float4 bv = *(const float4*)(b + tid * 4);
    float4 o4;
    o4.x = tf32r(d0 * rstd * gv.x + bv.x);
    o4.y = tf32r(d1 * rstd * gv.y + bv.y);
    o4.z = tf32r(d2 * rstd * gv.z + bv.z);
    o4.w = tf32r(d3 * rstd * gv.w + bv.w);
    *(float4*)(o + (size_t)row * D_ + tid * 4) = o4;
}

// ------------------------- weight transpose + tf32 round --------------------
__global__ __launch_bounds__(256) void ttf32_kernel(
    const float* __restrict__ W, float* __restrict__ T, int K, int N)
{
    __shared__ float t[32][33];
    const int tx = threadIdx.x, ty = threadIdx.y;
    const int n0 = blockIdx.x * 32, k0 = blockIdx.y * 32;
    #pragma unroll
    for (int r = 0; r < 4; r++)
        t[ty + r*8][tx] = W[(size_t)(k0 + ty + r*8) * N + n0 + tx];
    __syncthreads();
    #pragma unroll
    for (int r = 0; r < 4; r++)
        T[(size_t)(n0 + ty + r*8) * K + k0 + tx] = tf32r(t[tx][ty + r*8]);
}

__global__ void pack_bias_kernel(const float* __restrict__ bq,
                                 const float* __restrict__ bk,
                                 const float* __restrict__ bv,
                                 float* __restrict__ o)
{
    const int i = blockIdx.x * 256 + threadIdx.x;
    if (i < 1024)       o[i] = bq[i];
    else if (i < 2048)  o[i] = bk[i - 1024];
    else                o[i] = bv[i - 2048];
}

// ------------------------- tf32 GEMM ----------------------------------------
// C[M,N] = A[M,K] @ W[K,N]; A fp32(tf32), W^T fp32(tf32) [N,K].
// 128x128 CTA tile, BK=32 chunk, 8 warps (64x32 warp tiles), 2-stage cp.async.
// Smem tile: 128 rows x 36 floats (144 B row stride -> conflict-free LDS.32).
// OUT: 0 = fp32 raw, 1 = tf32-rounded fp32, 2 = packed bf16.
#define GT_TILE  18432
#define GT_STAGE 36864
#define GSMEM    73728

template<int OUT, bool RELU, bool RES, bool QKVA>
__global__ __launch_bounds__(256, 2) void tf32_gemm(
    const float* __restrict__ A, const float* __restrict__ Bw,
    const float* __restrict__ bias, const float* __restrict__ res,
    float* __restrict__ C, bf16* __restrict__ Cb, int M, int N, int K)
{
    extern __shared__ char smem[];
    const u32 sbase = smem_u32(smem);

    const int tid = threadIdx.x;
    const int wid = tid >> 5;
    const int lid = tid & 31;
    const int wr  = wid & 1;
    const int wc  = wid >> 1;
    const int bm  = blockIdx.y * 128;
    const int bn  = blockIdx.x * 128;

    const float* srcs[2] = {A, Bw};
    const int    rb  [2] = {bm, bn};
    const int nch = K >> 5;

    // 8 cp.async(16B) per thread per stage: 2 tiles x 128 rows x 8 segs
    int l_tile[8], l_seg[8];
    size_t l_grow[8];
    u32 l_sm[8];
    #pragma unroll
    for (int it = 0; it < 8; it++) {
        const int idx = tid + it * 256;
        const int tile = idx >> 10;
        const int r    = (idx >> 3) & 127;
        const int seg  = idx & 7;
        l_tile[it] = tile;
        l_seg[it]  = seg;
        l_grow[it] = (size_t)(rb[tile] + r);
        l_sm[it]   = tile * GT_TILE + r * 144 + seg * 16;
    }

    auto load_chunk = [&](int i, int st) {
        const size_t kc = (size_t)i * 32;
        const u32 so = sbase + st * GT_STAGE;
        #pragma unroll
        for (int it = 0; it < 8; it++) {
            const float* gp = srcs[l_tile[it]] + l_grow[it] * (size_t)K + kc + l_seg[it] * 4;
            CP_ASYNC16(so + l_sm[it], gp);
        }
        CP_COMMIT();
    };

    float acc[4][4][4];
    #pragma unroll
    for (int i = 0; i < 4; i++)
        #pragma unroll
        for (int j = 0; j < 4; j++)
            #pragma unroll
            for (int f = 0; f < 4; f++) acc[i][j][f] = 0.f;

    // fragment lane offsets (row stride 144 B)
    const u32 a_lane = (u32)((wr*64 + (lid >> 2)) * 144 + (lid & 3) * 4);
    const u32 b_lane = (u32)((wc*32 + (lid >> 2)) * 144 + (lid & 3) * 4);

    load_chunk(0, 0);

    for (int i = 0; i < nch; i++) {
        const int st = i & 1;
        if (i + 1 < nch) { load_chunk(i + 1, st ^ 1); CP_WAIT(1); }
        else { CP_WAIT(0); }
        __syncthreads();

        const u32 so = sbase + st * GT_STAGE;
        const u32 aB = so + a_lane;
        const u32 bB = so + GT_TILE + b_lane;

        #pragma unroll
        for (int ks = 0; ks < 4; ks++) {
            const u32 ko = ks * 32;   // 8 floats
            u32 fa[4][4];
            #pragma unroll
            for (int am = 0; am < 4; am++) {
                const u32 ad = aB + am * (16*144) + ko;
                LDS32(fa[am][0], ad);
                LDS32(fa[am][1], ad + 8*144);
                LDS32(fa[am][2], ad + 16);
                LDS32(fa[am][3], ad + 8*144 + 16);
            }
            u32 fb[4][2];
            #pragma unroll
            for (int nt = 0; nt < 4; nt++) {
                const u32 bd = bB + nt * (8*144) + ko;
                LDS32(fb[nt][0], bd);
                LDS32(fb[nt][1], bd + 16);
            }
            #pragma unroll
            for (int am = 0; am < 4; am++)
                #pragma unroll
                for (int nt = 0; nt < 4; nt++)
                    MMA_TF32(acc[am][nt], fa[am], fb[nt]);
        }
        __syncthreads();
    }

    const int r0 = bm + wr*64 + (lid >> 2);
    const int c0 = bn + wc*32 + (lid & 3) * 2;
    #pragma unroll
    for (int am = 0; am < 4; am++) {
        #pragma unroll
        for (int bt = 0; bt < 4; bt++) {
            const int col = c0 + bt * 8;
            const float2 bv = *(const float2*)(bias + col);
            const float alpha = QKVA ? ((col < 1024) ? 0.125f : 1.0f) : 1.0f;
            #pragma unroll
            for (int half = 0; half < 2; half++) {
                const int row = r0 + am*16 + half*8;
                float v0 = (acc[am][bt][half*2 + 0] + bv.x) * alpha;
                float v1 = (acc[am][bt][half*2 + 1] + bv.y) * alpha;
                if (RELU) { v0 = fmaxf(v0, 0.f); v1 = fmaxf(v1, 0.f); }
                if (RES) {
                    const float2 rr = *(const float2*)(res + (size_t)row * N + col);
                    v0 += rr.x; v1 += rr.y;
                }
                if (OUT == 2) {
                    *(u32*)(Cb + (size_t)row * N + col) = pack_bf2(v0, v1);
                } else {
                    float2 o;
                    if (OUT == 1) { o.x = tf32r(v0); o.y = tf32r(v1); }
                    else          { o.x = v0;        o.y = v1; }
                    *(float2*)(C + (size_t)row * N + col) = o;
                }
            }
        }
    }
}

// ------------------------- HMMA flash attention ------------------------------
// Q/K/V are column slices of the packed bf16 QKV buffer (row stride QKVN).
#define AQ_OFF   0
#define AK_OFF(st) (18432 + (st)*9216)
#define AV_OFF(st) (36864 + (st)*9216)
#define AM_OFF(st) (55296 + (st)*256)
#define ASMEM    55808

__global__ __launch_bounds__(256) void attn_mma_kernel(
    const bf16* __restrict__ QKV, const int* __restrict__ mask,
    float* __restrict__ O)
{
    extern __shared__ char sm[];
    const u32 sb = smem_u32(sm);
    const int tid = threadIdx.x;
    const int wid = tid >> 5;
    const int lid = tid & 31;
    const int h = blockIdx.y;
    const int b = blockIdx.z;
    const size_t qrow0 = (size_t)(b * S_ + blockIdx.x * 128);

    const bf16* Q = QKV;
    const bf16* K = QKV + 1024;
    const bf16* V = QKV + 2048;

    for (int t = tid; t < 1024; t += 256) {
        const int r = t >> 3, cseg = t & 7;
        const uint4 v = *(const uint4*)(Q + (qrow0 + r) * QKVN + h * 64 + cseg * 8);
        *(uint4*)(sm + AQ_OFF + r * 144 + cseg * 16) = v;
    }
    __syncthreads();

    u32 qf[4][4];
    const u32 qaddr = sb + AQ_OFF + (u32)((wid * 16 + (lid & 15)) * 144 + (lid >> 4) * 16);
    #pragma unroll
    for (int ks = 0; ks < 4; ks++)
        LDSM_X4(qf[ks][0], qf[ks][1], qf[ks][2], qf[ks][3], qaddr + ks * 32);

    float m0 = -INFINITY, m1 = -INFINITY, l0 = 0.f, l1 = 0.f;
    float o[8][4];
    #pragma unroll
    for (int t = 0; t < 8; t++)
        #pragma unroll
        for (int f = 0; f < 4; f++) o[t][f] = 0.f;

    auto load_kv = [&](int jt, int st) {
        const size_t krow0 = (size_t)(b * S_ + jt * 64);
        #pragma unroll
        for (int it = 0; it < 4; it++) {
            const int t = tid + it * 256;
            const int tile = t >> 9;
            const int r = (t >> 3) & 63;
            const int cseg = t & 7;
            const bf16* src = (tile ? V : K) + (krow0 + r) * QKVN + h * 64 + cseg * 8;
            const u32 dst = sb + (tile ? AV_OFF(st) : AK_OFF(st)) + (u32)(r * 144 + cseg * 16);
            CP_ASYNC16(dst, src);
        }
        if (tid < 64) {
            const int mv = mask[b * S_ + jt * 64 + tid];
            *(float*)(sm + AM_OFF(st) + tid * 4) = mv ? 0.f : -1e9f;
        }
        CP_COMMIT();
    };

    load_kv(0, 0);

    const int ntiles = S_ / 64;
    for (int jt = 0; jt < ntiles; jt++) {
        const int st = jt & 1;
        if (jt + 1 < ntiles) { load_kv(jt + 1, st ^ 1); CP_WAIT(1); }
        else { CP_WAIT(0); }
        __syncthreads();

        float s[8][4];
        #pragma unroll
        for (int t = 0; t < 8; t++)
            #pragma unroll
            for (int f = 0; f < 4; f++) s[t][f] = 0.f;

        const u32 kaddr = sb + AK_OFF(st) + (u32)(((lid & 15)) * 144 + (lid >> 4) * 16);
        #pragma unroll
        for (int ks = 0; ks < 4; ks++) {
            #pragma unroll
            for (int nt2 = 0; nt2 < 4; nt2++) {
                u32 r0, r1, r2, r3;
                LDSM_X4(r0, r1, r2, r3, kaddr + nt2 * (16*144) + ks * 32);
                u32 bA[2] = {r0, r2};
                u32 bB[2] = {r1, r3};
                MMA_BF16(s[nt2*2],     qf[ks], bA);
                MMA_BF16(s[nt2*2 + 1], qf[ks], bB);
            }
        }

        float mx0 = -INFINITY, mx1 = -INFINITY;
        #pragma unroll
        for (int t = 0; t < 8; t++) {
            const float ma = *(const float*)(sm + AM_OFF(st) + (t*8 + (lid & 3)*2) * 4);
            const float mb = *(const float*)(sm + AM_OFF(st) + (t*8 + (lid & 3)*2 + 1) * 4);
            s[t][0] += ma; s[t][1] += mb; s[t][2] += ma; s[t][3] += mb;
            mx0 = fmaxf(mx0, fmaxf(s[t][0], s[t][1]));
            mx1 = fmaxf(mx1, fmaxf(s[t][2], s[t][3]));
        }
        mx0 = fmaxf(mx0, __shfl_xor_sync(0xffffffffu, mx0, 1));
        mx0 = fmaxf(mx0, __shfl_xor_sync(0xffffffffu, mx0, 2));
        mx1 = fmaxf(mx1, __shfl_xor_sync(0xffffffffu, mx1, 1));
        mx1 = fmaxf(mx1, __shfl_xor_sync(0xffffffffu, mx1, 2));

        const float nm0 = fmaxf(m0, mx0);
        const float nm1 = fmaxf(m1, mx1);
        const float f0 = __expf(m0 - nm0);
        const float f1 = __expf(m1 - nm1);
        m0 = nm0; m1 = nm1;
        l0 *= f0;  l1 *= f1;
        #pragma unroll
        for (int t = 0; t < 8; t++) {
            o[t][0] *= f0; o[t][1] *= f0;
            o[t][2] *= f1; o[t][3] *= f1;
        }

        u32 pa[4][4];
        float ps0 = 0.f, ps1 = 0.f;
        #pragma unroll
        for (int t = 0; t < 8; t++) {
            const float p0 = __expf(s[t][0] - m0);
            const float p1 = __expf(s[t][1] - m0);
            const float p2 = __expf(s[t][2] - m1);
            const float p3 = __expf(s[t][3] - m1);
            ps0 += p0 + p1; ps1 += p2 + p3;
            pa[t >> 1][(t & 1) * 2]     = pack_bf2(p0, p1);
            pa[t >> 1][(t & 1) * 2 + 1] = pack_bf2(p2, p3);
        }
        ps0 += __shfl_xor_sync(0xffffffffu, ps0, 1);
        ps0 += __shfl_xor_sync(0xffffffffu, ps0, 2);
        ps1 += __shfl_xor_sync(0xffffffffu, ps1, 1);
        ps1 += __shfl_xor_sync(0xffffffffu, ps1, 2);
        l0 += ps0; l1 += ps1;

        const u32 vaddr = sb + AV_OFF(st) + (u32)(((lid & 15)) * 144 + (lid >> 4) * 16);
        #pragma unroll
        for (int ks = 0; ks < 4; ks++) {
            #pragma unroll
            for (int dt2 = 0; dt2 < 4; dt2++) {
                u32 r0, r1, r2, r3;
                LDSM_X4_T(r0, r1, r2, r3, vaddr + ks * (16*144) + dt2 * 32);
                u32 bA[2] = {r0, r1};
                u32 bB[2] = {r2, r3};
                MMA_BF16(o[dt2*2],     pa[ks], bA);
                MMA_BF16(o[dt2*2 + 1], pa[ks], bB);
            }
        }
        __syncthreads();
    }

    const float inv0 = (l0 > 0.f) ? 1.f / l0 : 0.f;
    const float inv1 = (l1 > 0.f) ? 1.f / l1 : 0.f;
    const size_t row0 = qrow0 + wid * 16 + (lid >> 2);
    const int colb = h * 64 + (lid & 3) * 2;
    #pragma unroll
    for (int t = 0; t < 8; t++) {
        const int col = colb + t * 8;
        float2 oA, oB;
        oA.x = tf32r(o[t][0] * inv0); oA.y = tf32r(o[t][1] * inv0);
        oB.x = tf32r(o[t][2] * inv1); oB.y = tf32r(o[t][3] * inv1);
        *(float2*)(O + row0 * D_ + col)       = oA;
        *(float2*)(O + (row0 + 8) * D_ + col) = oB;
    }
}

// ------------------------- launch -------------------------------------------
extern "C" void kernel_launch(void* const* d_in, const int* in_sizes, int n_in,
                              void* d_out, int out_size)
{
    const float* x    = (const float*)d_in[0];
    const int*   mask = (const int*)  d_in[1];
    const float* wq   = (const float*)d_in[2];
    const float* bq   = (const float*)d_in[3];
    const float* wk   = (const float*)d_in[4];
    const float* bk   = (const float*)d_in[5];
    const float* wv   = (const float*)d_in[6];
    const float* bv   = (const float*)d_in[7];
    const float* wo   = (const float*)d_in[8];
    const float* bo   = (const float*)d_in[9];
    const float* g1   = (const float*)d_in[10];
    const float* be1  = (const float*)d_in[11];
    const float* g2   = (const float*)d_in[12];
    const float* be2  = (const float*)d_in[13];
    const float* w1   = (const float*)d_in[14];
    const float* bf1  = (const float*)d_in[15];
    const float* w2   = (const float*)d_in[16];
    const float* bf2  = (const float*)d_in[17];
    float* out = (float*)d_out;

    void* p;
    cudaGetSymbolAddress(&p, g_xn);    float* xn    = (float*)p;
    cudaGetSymbolAddress(&p, g_qkv);   bf16*  qkv   = (bf16*)p;
    cudaGetSymbolAddress(&p, g_att);   float* att   = (float*)p;
    cudaGetSymbolAddress(&p, g_x2);    float* x2    = (float*)p;
    cudaGetSymbolAddress(&p, g_h);     float* hb    = (float*)p;
    cudaGetSymbolAddress(&p, g_wqkvT); float* wqkvT = (float*)p;
    cudaGetSymbolAddress(&p, g_bqkv);  float* bqkv  = (float*)p;
    cudaGetSymbolAddress(&p, g_woT);   float* woT   = (float*)p;
    cudaGetSymbolAddress(&p, g_w1T);   float* w1T   = (float*)p;
    cudaGetSymbolAddress(&p, g_w2T);   float* w2T   = (float*)p;

    cudaFuncSetAttribute(tf32_gemm<2,false,false,true >, cudaFuncAttributeMaxDynamicSharedMemorySize, GSMEM);
    cudaFuncSetAttribute(tf32_gemm<0,false,true ,false>, cudaFuncAttributeMaxDynamicSharedMemorySize, GSMEM);
    cudaFuncSetAttribute(tf32_gemm<1,true ,false,false>, cudaFuncAttributeMaxDynamicSharedMemorySize, GSMEM);
    cudaFuncSetAttribute(attn_mma_kernel, cudaFuncAttributeMaxDynamicSharedMemorySize, ASMEM);

    const dim3 tb(32, 8);
    ttf32_kernel<<<dim3(D_/32, D_/32), tb>>>(wq, wqkvT,           D_, D_);
    ttf32_kernel<<<dim3(D_/32, D_/32), tb>>>(wk, wqkvT + 1024*D_, D_, D_);
    ttf32_kernel<<<dim3(D_/32, D_/32), tb>>>(wv, wqkvT + 2048*D_, D_, D_);
    ttf32_kernel<<<dim3(D_/32, D_/32), tb>>>(wo, woT, D_, D_);
    ttf32_kernel<<<dim3(F_/32, D_/32), tb>>>(w1, w1T, D_, F_);
    ttf32_kernel<<<dim3(D_/32, F_/32), tb>>>(w2, w2T, F_, D_);
    pack_bias_kernel<<<QKVN/256, 256>>>(bq, bk, bv, bqkv);

    ln_kernel<<<M_, 256>>>(x, g1, be1, xn);

    // fused QKV GEMM -> packed bf16 [M, 3072] (Q cols pre-scaled by 1/8)
    const dim3 gQKV(QKVN/128, M_/128);
    tf32_gemm<2,false,false,true><<<gQKV, 256, GSMEM>>>(xn, wqkvT, bqkv, nullptr, nullptr, qkv, M_, QKVN, D_);

    dim3 attG(S_/128, H_, B_);
    attn_mma_kernel<<<attG, 256, ASMEM>>>(qkv, mask, att);

    const dim3 gD(D_/128, M_/128);
    tf32_gemm<0,false,true,false><<<gD, 256, GSMEM>>>(att, woT, bo, x, x2, nullptr, M_, D_, D_);

    ln_kernel<<<M_, 256>>>(x2, g2, be2, xn);

    const dim3 gF(F_/128, M_/128);
    tf32_gemm<1,true,false,false><<<gF, 256, GSMEM>>>(xn, w1T, bf1, nullptr, hb, nullptr, M_, F_, D_);

    tf32_gemm<0,false,true,false><<<gD, 256, GSMEM>>>(hb, w2T, bf2, x2, out, nullptr, M_, D_, F_);
}

// round 7
// speedup vs baseline: 6.4628x; 1.4293x over previous
#include <cuda_runtime.h>
#include <cuda_fp16.h>
#include <math.h>

typedef unsigned int u32;
typedef unsigned long long u64;

#define B_   2
#define S_   2048
#define D_   1024
#define H_   16
#define F_   4096
#define M_   (B_*S_)
#define QKVN 3072

// ------------------------- scratch (device globals) -------------------------
__device__ __align__(16) __half g_xn[M_*D_];               // LN out fp16
__device__ __align__(16) __half g_qkv[(size_t)M_*QKVN];    // packed QKV fp16
__device__ __align__(16) __half g_att[M_*D_];              // attn out fp16
__device__ __align__(16) float  g_x2[M_*D_];               // residual fp32
__device__ __align__(16) __half g_h[(size_t)M_*F_];        // FFN hidden fp16
__device__ __align__(16) __half g_wqkvT[(size_t)QKVN*D_];  // transposed fp16 weights
__device__ __align__(16) float  g_bqkv[QKVN];
__device__ __align__(16) __half g_woT[D_*D_];
__device__ __align__(16) __half g_w1T[(size_t)F_*D_];
__device__ __align__(16) __half g_w2T[(size_t)D_*F_];

// ------------------------- helpers ------------------------------------------
__device__ __forceinline__ u32 smem_u32(const void* p) {
    u32 a;
    asm("{ .reg .u64 t; cvta.to.shared.u64 t, %1; cvt.u32.u64 %0, t; }"
        : "=r"(a) : "l"(p));
    return a;
}
#define CP_ASYNC16(sm, gp) \
    asm volatile("cp.async.cg.shared.global [%0], [%1], 16;" :: "r"(sm), "l"(gp))
#define CP_COMMIT() asm volatile("cp.async.commit_group;" ::: "memory")
#define CP_WAIT(n)  asm volatile("cp.async.wait_group %0;" :: "n"(n) : "memory")

#define LDSM_X4(r0,r1,r2,r3,a) \
    asm volatile("ldmatrix.sync.aligned.m8n8.x4.shared.b16 {%0,%1,%2,%3}, [%4];" \
        : "=r"(r0), "=r"(r1), "=r"(r2), "=r"(r3) : "r"(a))
#define LDSM_X4_T(r0,r1,r2,r3,a) \
    asm volatile("ldmatrix.sync.aligned.m8n8.x4.trans.shared.b16 {%0,%1,%2,%3}, [%4];" \
        : "=r"(r0), "=r"(r1), "=r"(r2), "=r"(r3) : "r"(a))

#define MMA_F16(d, a, b) \
    asm volatile("mma.sync.aligned.m16n8k16.row.col.f32.f16.f16.f32 " \
        "{%0,%1,%2,%3}, {%4,%5,%6,%7}, {%8,%9}, {%0,%1,%2,%3};" \
        : "+f"((d)[0]), "+f"((d)[1]), "+f"((d)[2]), "+f"((d)[3]) \
        : "r"((a)[0]), "r"((a)[1]), "r"((a)[2]), "r"((a)[3]), \
          "r"((b)[0]), "r"((b)[1]))

__device__ __forceinline__ u32 pack_h2(float a, float b) {
    __half2 t = __floats2half2_rn(a, b);
    return *(u32*)&t;
}

// ------------------------- layernorm (fp16 out) ------------------------------
__global__ __launch_bounds__(256) void ln_kernel(
    const float* __restrict__ x, const float* __restrict__ g,
    const float* __restrict__ b, __half* __restrict__ o)
{
    __shared__ float red[8];
    const int row = blockIdx.x;
    const int tid = threadIdx.x;
    const float* xr = x + (size_t)row * D_;

    float4 xv = *(const float4*)(xr + tid * 4);
    float s = xv.x + xv.y + xv.z + xv.w;
    #pragma unroll
    for (int of = 16; of > 0; of >>= 1) s += __shfl_xor_sync(0xffffffffu, s, of);
    if ((tid & 31) == 0) red[tid >> 5] = s;
    __syncthreads();
    float tot = 0.f;
    #pragma unroll
    for (int w = 0; w < 8; w++) tot += red[w];
    const float mean = tot * (1.0f / D_);

    float d0 = xv.x - mean, d1 = xv.y - mean, d2 = xv.z - mean, d3 = xv.w - mean;
    float sq = d0*d0 + d1*d1 + d2*d2 + d3*d3;
    __syncthreads();
    #pragma unroll
    for (int of = 16; of > 0; of >>= 1) sq += __shfl_xor_sync(0xffffffffu, sq, of);
    if ((tid & 31) == 0) red[tid >> 5] = sq;
    __syncthreads();
    float vtot = 0.f;
    #pragma unroll
    for (int w = 0; w < 8; w++) vtot += red[w];
    const float rstd = rsqrtf(vtot * (1.0f / D_) + 1e-5f);

    float4 gv = *(const float4*)(g + tid * 4);
    float4 bv = *(const float4*)(b + tid * 4);
    const size_t off = (size_t)row * D_ + tid * 4;
    u32 p0 = pack_h2(d0 * rstd * gv.x + bv.x, d1 * rstd * gv.y + bv.y);
    u32 p1 = pack_h2(d2 * rstd * gv.z + bv.z, d3 * rstd * gv.w + bv.w);
    uint2 pk; pk.x = p0; pk.y = p1;
    *(uint2*)(o + off) = pk;
}

// ------------------------- weight transpose + fp16 --------------------------
__global__ __launch_bounds__(256) void thalf_kernel(
    const float* __restrict__ W, __half* __restrict__ T, int K, int N)
{
    __shared__ float t[32][33];
    const int tx = threadIdx.x, ty = threadIdx.y;
    const int n0 = blockIdx.x * 32, k0 = blockIdx.y * 32;
    #pragma unroll
    for (int r = 0; r < 4; r++)
        t[ty + r*8][tx] = W[(size_t)(k0 + ty + r*8) * N + n0 + tx];
    __syncthreads();
    #pragma unroll
    for (int r = 0; r < 4; r++)
        T[(size_t)(n0 + ty + r*8) * K + k0 + tx] = __float2half_rn(t[tx][ty + r*8]);
}

__global__ void pack_bias_kernel(const float* __restrict__ bq,
                                 const float* __restrict__ bk,
                                 const float* __restrict__ bv,
                                 float* __restrict__ o)
{
    const int i = blockIdx.x * 256 + threadIdx.x;
    if (i < 1024)       o[i] = bq[i];
    else if (i < 2048)  o[i] = bk[i - 1024];
    else                o[i] = bv[i - 2048];
}

// ------------------------- fp16 HMMA GEMM -----------------------------------
// C[M,N] = A[M,K] @ W[K,N]; A fp16 [M,K], W^T fp16 [N,K].
// 128x128 CTA tile, BK=32 chunk, 8 warps (64x32 warp tiles), 3-stage cp.async.
// Smem tile: 128 rows x (32+8) halves (80 B row stride).
// OUT: 0 = fp32 (+res), 2 = packed fp16.
#define TROWB 80
#define TILEB (128*TROWB)
#define STAGEB (2*TILEB)
#define GSMEM  (3*STAGEB)

template<int OUT, bool RELU, bool RES, bool QKVA>
__global__ __launch_bounds__(256, 2) void h16_gemm(
    const __half* __restrict__ A, const __half* __restrict__ Bw,
    const float* __restrict__ bias, const float* __restrict__ res,
    float* __restrict__ C, __half* __restrict__ Cb, int M, int N, int K)
{
    extern __shared__ char smem[];
    const u32 sbase = smem_u32(smem);

    const int tid = threadIdx.x;
    const int wid = tid >> 5;
    const int lid = tid & 31;
    const int wr  = wid & 1;
    const int wc  = wid >> 1;
    const int bm  = blockIdx.y * 128;
    const int bn  = blockIdx.x * 128;

    const __half* srcs[2] = {A, Bw};
    const int     rb  [2] = {bm, bn};
    const int nch = K >> 5;

    // 4 cp.async(16B) per thread per stage: 2 tiles x 128 rows x 4 segs
    int l_tile[4], l_seg[4];
    size_t l_grow[4];
    u32 l_sm[4];
    #pragma unroll
    for (int it = 0; it < 4; it++) {
        const int idx = tid + it * 256;
        const int tile = idx >> 9;
        const int r    = (idx >> 2) & 127;
        const int seg  = idx & 3;
        l_tile[it] = tile;
        l_seg[it]  = seg;
        l_grow[it] = (size_t)(rb[tile] + r);
        l_sm[it]   = tile * TILEB + r * TROWB + seg * 16;
    }

    auto load_chunk = [&](int i, int st) {
        const size_t kc = (size_t)i * 32;
        const u32 so = sbase + st * STAGEB;
        #pragma unroll
        for (int it = 0; it < 4; it++) {
            const __half* gp = srcs[l_tile[it]] + l_grow[it] * (size_t)K + kc + l_seg[it] * 8;
            CP_ASYNC16(so + l_sm[it], gp);
        }
        CP_COMMIT();
    };

    float acc[4][4][4];
    #pragma unroll
    for (int i = 0; i < 4; i++)
        #pragma unroll
        for (int j = 0; j < 4; j++)
            #pragma unroll
            for (int f = 0; f < 4; f++) acc[i][j][f] = 0.f;

    const u32 a_lane = (u32)((wr*64 + (lid & 15)) * TROWB + (lid >> 4) * 16);
    const u32 b_lane = (u32)((wc*32 + (lid & 15)) * TROWB + (lid >> 4) * 16);

    load_chunk(0, 0);
    load_chunk(1, 1);

    for (int i = 0; i < nch; i++) {
        const int st = i % 3;
        if (i + 2 < nch) { load_chunk(i + 2, (i + 2) % 3); CP_WAIT(2); }
        else if (i + 1 < nch) { CP_WAIT(1); }
        else { CP_WAIT(0); }
        __syncthreads();

        const u32 so = sbase + st * STAGEB;
        const u32 aB = so + a_lane;
        const u32 bB = so + TILEB + b_lane;

        #pragma unroll
        for (int ks = 0; ks < 2; ks++) {
            const u32 ko = ks * 32;
            u32 fa[4][4];
            #pragma unroll
            for (int am = 0; am < 4; am++)
                LDSM_X4(fa[am][0], fa[am][1], fa[am][2], fa[am][3],
                        aB + am * (16*TROWB) + ko);
            u32 fb[4][2];
            #pragma unroll
            for (int bt2 = 0; bt2 < 2; bt2++) {
                u32 r0, r1, r2, r3;
                LDSM_X4(r0, r1, r2, r3, bB + bt2 * (16*TROWB) + ko);
                fb[bt2*2  ][0] = r0; fb[bt2*2  ][1] = r2;
                fb[bt2*2+1][0] = r1; fb[bt2*2+1][1] = r3;
            }
            #pragma unroll
            for (int am = 0; am < 4; am++)
                #pragma unroll
                for (int nt = 0; nt < 4; nt++)
                    MMA_F16(acc[am][nt], fa[am], fb[nt]);
        }
        __syncthreads();
    }

    const int r0 = bm + wr*64 + (lid >> 2);
    const int c0 = bn + wc*32 + (lid & 3) * 2;
    #pragma unroll
    for (int am = 0; am < 4; am++) {
        #pragma unroll
        for (int bt = 0; bt < 4; bt++) {
            const int col = c0 + bt * 8;
            const float2 bv = *(const float2*)(bias + col);
            const float alpha = QKVA ? ((col < 1024) ? 0.125f : 1.0f) : 1.0f;
            #pragma unroll
            for (int half = 0; half < 2; half++) {
                const int row = r0 + am*16 + half*8;
                float v0 = (acc[am][bt][half*2 + 0] + bv.x) * alpha;
                float v1 = (acc[am][bt][half*2 + 1] + bv.y) * alpha;
                if (RELU) { v0 = fmaxf(v0, 0.f); v1 = fmaxf(v1, 0.f); }
                if (RES) {
                    const float2 rr = *(const float2*)(res + (size_t)row * N + col);
                    v0 += rr.x; v1 += rr.y;
                }
                if (OUT == 2) {
                    *(u32*)(Cb + (size_t)row * N + col) = pack_h2(v0, v1);
                } else {
                    float2 o; o.x = v0; o.y = v1;
                    *(float2*)(C + (size_t)row * N + col) = o;
                }
            }
        }
    }
}

// ------------------------- fp16 HMMA flash attention -------------------------
// Q/K/V are column slices of packed fp16 QKV (row stride QKVN). Q pre-scaled.
#define AQ_OFF   0
#define AK_OFF(st) (18432 + (st)*9216)
#define AV_OFF(st) (36864 + (st)*9216)
#define AM_OFF(st) (55296 + (st)*256)
#define ASMEM    55808

__global__ __launch_bounds__(256) void attn_mma_kernel(
    const __half* __restrict__ QKV, const int* __restrict__ mask,
    __half* __restrict__ O)
{
    extern __shared__ char sm[];
    const u32 sb = smem_u32(sm);
    const int tid = threadIdx.x;
    const int wid = tid >> 5;
    const int lid = tid & 31;
    const int h = blockIdx.y;
    const int b = blockIdx.z;
    const size_t qrow0 = (size_t)(b * S_ + blockIdx.x * 128);

    const __half* Q = QKV;
    const __half* K = QKV + 1024;
    const __half* V = QKV + 2048;

    for (int t = tid; t < 1024; t += 256) {
        const int r = t >> 3, cseg = t & 7;
        const uint4 v = *(const uint4*)(Q + (qrow0 + r) * QKVN + h * 64 + cseg * 8);
        *(uint4*)(sm + AQ_OFF + r * 144 + cseg * 16) = v;
    }
    __syncthreads();

    u32 qf[4][4];
    const u32 qaddr = sb + AQ_OFF + (u32)((wid * 16 + (lid & 15)) * 144 + (lid >> 4) * 16);
    #pragma unroll
    for (int ks = 0; ks < 4; ks++)
        LDSM_X4(qf[ks][0], qf[ks][1], qf[ks][2], qf[ks][3], qaddr + ks * 32);

    float m0 = -INFINITY, m1 = -INFINITY, l0 = 0.f, l1 = 0.f;
    float o[8][4];
    #pragma unroll
    for (int t = 0; t < 8; t++)
        #pragma unroll
        for (int f = 0; f < 4; f++) o[t][f] = 0.f;

    auto load_kv = [&](int jt, int st) {
        const size_t krow0 = (size_t)(b * S_ + jt * 64);
        #pragma unroll
        for (int it = 0; it < 4; it++) {
            const int t = tid + it * 256;
            const int tile = t >> 9;
            const int r = (t >> 3) & 63;
            const int cseg = t & 7;
            const __half* src = (tile ? V : K) + (krow0 + r) * QKVN + h * 64 + cseg * 8;
            const u32 dst = sb + (tile ? AV_OFF(st) : AK_OFF(st)) + (u32)(r * 144 + cseg * 16);
            CP_ASYNC16(dst, src);
        }
        if (tid < 64) {
            const int mv = mask[b * S_ + jt * 64 + tid];
            *(float*)(sm + AM_OFF(st) + tid * 4) = mv ? 0.f : -1e9f;
        }
        CP_COMMIT();
    };

    load_kv(0, 0);

    const int ntiles = S_ / 64;
    for (int jt = 0; jt < ntiles; jt++) {
        const int st = jt & 1;
        if (jt + 1 < ntiles) { load_kv(jt + 1, st ^ 1); CP_WAIT(1); }
        else { CP_WAIT(0); }
        __syncthreads();

        float s[8][4];
        #pragma unroll
        for (int t = 0; t < 8; t++)
            #pragma unroll
            for (int f = 0; f < 4; f++) s[t][f] = 0.f;

        const u32 kaddr = sb + AK_OFF(st) + (u32)(((lid & 15)) * 144 + (lid >> 4) * 16);
        #pragma unroll
        for (int ks = 0; ks < 4; ks++) {
            #pragma unroll
            for (int nt2 = 0; nt2 < 4; nt2++) {
                u32 r0, r1, r2, r3;
                LDSM_X4(r0, r1, r2, r3, kaddr + nt2 * (16*144) + ks * 32);
                u32 bA[2] = {r0, r2};
                u32 bB[2] = {r1, r3};
                MMA_F16(s[nt2*2],     qf[ks], bA);
                MMA_F16(s[nt2*2 + 1], qf[ks], bB);
            }
        }

        float mx0 = -INFINITY, mx1 = -INFINITY;
        #pragma unroll
        for (int t = 0; t < 8; t++) {
            const float ma = *(const float*)(sm + AM_OFF(st) + (t*8 + (lid & 3)*2) * 4);
            const float mb = *(const float*)(sm + AM_OFF(st) + (t*8 + (lid & 3)*2 + 1) * 4);
            s[t][0] += ma; s[t][1] += mb; s[t][2] += ma; s[t][3] += mb;
            mx0 = fmaxf(mx0, fmaxf(s[t][0], s[t][1]));
            mx1 = fmaxf(mx1, fmaxf(s[t][2], s[t][3]));
        }
        mx0 = fmaxf(mx0, __shfl_xor_sync(0xffffffffu, mx0, 1));
        mx0 = fmaxf(mx0, __shfl_xor_sync(0xffffffffu, mx0, 2));
        mx1 = fmaxf(mx1, __shfl_xor_sync(0xffffffffu, mx1, 1));
        mx1 = fmaxf(mx1, __shfl_xor_sync(0xffffffffu, mx1, 2));

        const float nm0 = fmaxf(m0, mx0);
        const float nm1 = fmaxf(m1, mx1);
        const float f0 = __expf(m0 - nm0);
        const float f1 = __expf(m1 - nm1);
        m0 = nm0; m1 = nm1;
        l0 *= f0;  l1 *= f1;
        #pragma unroll
        for (int t = 0; t < 8; t++) {
            o[t][0] *= f0; o[t][1] *= f0;
            o[t][2] *= f1; o[t][3] *= f1;
        }

        u32 pa[4][4];
        float ps0 = 0.f, ps1 = 0.f;
        #pragma unroll
        for (int t = 0; t < 8; t++) {
            const float p0 = __expf(s[t][0] - m0);
            const float p1 = __expf(s[t][1] - m0);
            const float p2 = __expf(s[t][2] - m1);
            const float p3 = __expf(s[t][3] - m1);
            ps0 += p0 + p1; ps1 += p2 + p3;
            pa[t >> 1][(t & 1) * 2]     = pack_h2(p0, p1);
            pa[t >> 1][(t & 1) * 2 + 1] = pack_h2(p2, p3);
        }
        ps0 += __shfl_xor_sync(0xffffffffu, ps0, 1);
        ps0 += __shfl_xor_sync(0xffffffffu, ps0, 2);
        ps1 += __shfl_xor_sync(0xffffffffu, ps1, 1);
        ps1 += __shfl_xor_sync(0xffffffffu, ps1, 2);
        l0 += ps0; l1 += ps1;

        const u32 vaddr = sb + AV_OFF(st) + (u32)(((lid & 15)) * 144 + (lid >> 4) * 16);
        #pragma unroll
        for (int ks = 0; ks < 4; ks++) {
            #pragma unroll
            for (int dt2 = 0; dt2 < 4; dt2++) {
                u32 r0, r1, r2, r3;
                LDSM_X4_T(r0, r1, r2, r3, vaddr + ks * (16*144) + dt2 * 32);
                u32 bA[2] = {r0, r1};
                u32 bB[2] = {r2, r3};
                MMA_F16(o[dt2*2],     pa[ks], bA);
                MMA_F16(o[dt2*2 + 1], pa[ks], bB);
            }
        }
        __syncthreads();
    }

    const float inv0 = (l0 > 0.f) ? 1.f / l0 : 0.f;
    const float inv1 = (l1 > 0.f) ? 1.f / l1 : 0.f;
    const size_t row0 = qrow0 + wid * 16 + (lid >> 2);
    const int colb = h * 64 + (lid & 3) * 2;
    #pragma unroll
    for (int t = 0; t < 8; t++) {
        const int col = colb + t * 8;
        *(u32*)(O + row0 * D_ + col)       = pack_h2(o[t][0] * inv0, o[t][1] * inv0);
        *(u32*)(O + (row0 + 8) * D_ + col) = pack_h2(o[t][2] * inv1, o[t][3] * inv1);
    }
}

// ------------------------- launch -------------------------------------------
extern "C" void kernel_launch(void* const* d_in, const int* in_sizes, int n_in,
                              void* d_out, int out_size)
{
    const float* x    = (const float*)d_in[0];
    const int*   mask = (const int*)  d_in[1];
    const float* wq   = (const float*)d_in[2];
    const float* bq   = (const float*)d_in[3];
    const float* wk   = (const float*)d_in[4];
    const float* bk   = (const float*)d_in[5];
    const float* wv   = (const float*)d_in[6];
    const float* bv   = (const float*)d_in[7];
    const float* wo   = (const float*)d_in[8];
    const float* bo   = (const float*)d_in[9];
    const float* g1   = (const float*)d_in[10];
    const float* be1  = (const float*)d_in[11];
    const float* g2   = (const float*)d_in[12];
    const float* be2  = (const float*)d_in[13];
    const float* w1   = (const float*)d_in[14];
    const float* bf1  = (const float*)d_in[15];
    const float* w2   = (const float*)d_in[16];
    const float* bf2  = (const float*)d_in[17];
    float* out = (float*)d_out;

    void* p;
    cudaGetSymbolAddress(&p, g_xn);    __half* xn    = (__half*)p;
    cudaGetSymbolAddress(&p, g_qkv);   __half* qkv   = (__half*)p;
    cudaGetSymbolAddress(&p, g_att);   __half* att   = (__half*)p;
    cudaGetSymbolAddress(&p, g_x2);    float*  x2    = (float*)p;
    cudaGetSymbolAddress(&p, g_h);     __half* hb    = (__half*)p;
    cudaGetSymbolAddress(&p, g_wqkvT); __half* wqkvT = (__half*)p;
    cudaGetSymbolAddress(&p, g_bqkv);  float*  bqkv  = (float*)p;
    cudaGetSymbolAddress(&p, g_woT);   __half* woT   = (__half*)p;
    cudaGetSymbolAddress(&p, g_w1T);   __half* w1T   = (__half*)p;
    cudaGetSymbolAddress(&p, g_w2T);   __half* w2T   = (__half*)p;

    cudaFuncSetAttribute(h16_gemm<2,false,false,true >, cudaFuncAttributeMaxDynamicSharedMemorySize, GSMEM);
    cudaFuncSetAttribute(h16_gemm<0,false,true ,false>, cudaFuncAttributeMaxDynamicSharedMemorySize, GSMEM);
    cudaFuncSetAttribute(h16_gemm<2,true ,false,false>, cudaFuncAttributeMaxDynamicSharedMemorySize, GSMEM);
    cudaFuncSetAttribute(attn_mma_kernel, cudaFuncAttributeMaxDynamicSharedMemorySize, ASMEM);

    const dim3 tb(32, 8);
    thalf_kernel<<<dim3(D_/32, D_/32), tb>>>(wq, wqkvT,           D_, D_);
    thalf_kernel<<<dim3(D_/32, D_/32), tb>>>(wk, wqkvT + 1024*D_, D_, D_);
    thalf_kernel<<<dim3(D_/32, D_/32), tb>>>(wv, wqkvT + 2048*D_, D_, D_);
    thalf_kernel<<<dim3(D_/32, D_/32), tb>>>(wo, woT, D_, D_);
    thalf_kernel<<<dim3(F_/32, D_/32), tb>>>(w1, w1T, D_, F_);
    thalf_kernel<<<dim3(D_/32, F_/32), tb>>>(w2, w2T, F_, D_);
    pack_bias_kernel<<<QKVN/256, 256>>>(bq, bk, bv, bqkv);

    ln_kernel<<<M_, 256>>>(x, g1, be1, xn);

    // fused QKV GEMM -> packed fp16 [M, 3072] (Q cols pre-scaled by 1/8)
    const dim3 gQKV(QKVN/128, M_/128);
    h16_gemm<2,false,false,true><<<gQKV, 256, GSMEM>>>(xn, wqkvT, bqkv, nullptr, nullptr, qkv, M_, QKVN, D_);

    dim3 attG(S_/128, H_, B_);
    attn_mma_kernel<<<attG, 256, ASMEM>>>(qkv, mask, att);

    const dim3 gD(D_/128, M_/128);
    h16_gemm<0,false,true,false><<<gD, 256, GSMEM>>>(att, woT, bo, x, x2, nullptr, M_, D_, D_);

    ln_kernel<<<M_, 256>>>(x2, g2, be2, xn);

    const dim3 gF(F_/128, M_/128);
    h16_gemm<2,true,false,false><<<gF, 256, GSMEM>>>(xn, w1T, bf1, nullptr, nullptr, hb, M_, F_, D_);

    h16_gemm<0,false,true,false><<<gD, 256, GSMEM>>>(hb, w2T, bf2, x2, out, nullptr, M_, D_, F_);
}

// round 8
// speedup vs baseline: 7.0082x; 1.0844x over previous
#include <cuda_runtime.h>
#include <cuda_fp16.h>
#include <math.h>

typedef unsigned int u32;
typedef unsigned long long u64;

#define B_   2
#define S_   2048
#define D_   1024
#define H_   16
#define F_   4096
#define M_   (B_*S_)
#define QKVN 3072

// ------------------------- scratch (device globals) -------------------------
__device__ __align__(16) __half g_xn[M_*D_];
__device__ __align__(16) __half g_qkv[(size_t)M_*QKVN];
__device__ __align__(16) __half g_att[M_*D_];
__device__ __align__(16) float  g_x2[M_*D_];
__device__ __align__(16) __half g_h[(size_t)M_*F_];
__device__ __align__(16) __half g_wqkvT[(size_t)QKVN*D_];
__device__ __align__(16) float  g_bqkv[QKVN];
__device__ __align__(16) __half g_woT[D_*D_];
__device__ __align__(16) __half g_w1T[(size_t)F_*D_];
__device__ __align__(16) __half g_w2T[(size_t)D_*F_];

// ------------------------- helpers ------------------------------------------
__device__ __forceinline__ u32 smem_u32(const void* p) {
    u32 a;
    asm("{ .reg .u64 t; cvta.to.shared.u64 t, %1; cvt.u32.u64 %0, t; }"
        : "=r"(a) : "l"(p));
    return a;
}
#define CP_ASYNC16(sm, gp) \
    asm volatile("cp.async.cg.shared.global [%0], [%1], 16;" :: "r"(sm), "l"(gp))
#define CP_ASYNC4(sm, gp) \
    asm volatile("cp.async.ca.shared.global [%0], [%1], 4;" :: "r"(sm), "l"(gp))
#define CP_COMMIT() asm volatile("cp.async.commit_group;" ::: "memory")
#define CP_WAIT(n)  asm volatile("cp.async.wait_group %0;" :: "n"(n) : "memory")

#define LDSM_X4(r0,r1,r2,r3,a) \
    asm volatile("ldmatrix.sync.aligned.m8n8.x4.shared.b16 {%0,%1,%2,%3}, [%4];" \
        : "=r"(r0), "=r"(r1), "=r"(r2), "=r"(r3) : "r"(a))
#define LDSM_X4_T(r0,r1,r2,r3,a) \
    asm volatile("ldmatrix.sync.aligned.m8n8.x4.trans.shared.b16 {%0,%1,%2,%3}, [%4];" \
        : "=r"(r0), "=r"(r1), "=r"(r2), "=r"(r3) : "r"(a))

#define MMA_F16(d, a, b) \
    asm volatile("mma.sync.aligned.m16n8k16.row.col.f32.f16.f16.f32 " \
        "{%0,%1,%2,%3}, {%4,%5,%6,%7}, {%8,%9}, {%0,%1,%2,%3};" \
        : "+f"((d)[0]), "+f"((d)[1]), "+f"((d)[2]), "+f"((d)[3]) \
        : "r"((a)[0]), "r"((a)[1]), "r"((a)[2]), "r"((a)[3]), \
          "r"((b)[0]), "r"((b)[1]))

__device__ __forceinline__ u32 pack_h2(float a, float b) {
    __half2 t = __floats2half2_rn(a, b);
    return *(u32*)&t;
}

// ------------------------- layernorm (fp16 out) ------------------------------
__global__ __launch_bounds__(256) void ln_kernel(
    const float* __restrict__ x, const float* __restrict__ g,
    const float* __restrict__ b, __half* __restrict__ o)
{
    __shared__ float red[8];
    const int row = blockIdx.x;
    const int tid = threadIdx.x;
    const float* xr = x + (size_t)row * D_;

    float4 xv = *(const float4*)(xr + tid * 4);
    float s = xv.x + xv.y + xv.z + xv.w;
    #pragma unroll
    for (int of = 16; of > 0; of >>= 1) s += __shfl_xor_sync(0xffffffffu, s, of);
    if ((tid & 31) == 0) red[tid >> 5] = s;
    __syncthreads();
    float tot = 0.f;
    #pragma unroll
    for (int w = 0; w < 8; w++) tot += red[w];
    const float mean = tot * (1.0f / D_);

    float d0 = xv.x - mean, d1 = xv.y - mean, d2 = xv.z - mean, d3 = xv.w - mean;
    float sq = d0*d0 + d1*d1 + d2*d2 + d3*d3;
    __syncthreads();
    #pragma unroll
    for (int of = 16; of > 0; of >>= 1) sq += __shfl_xor_sync(0xffffffffu, sq, of);
    if ((tid & 31) == 0) red[tid >> 5] = sq;
    __syncthreads();
    float vtot = 0.f;
    #pragma unroll
    for (int w = 0; w < 8; w++) vtot += red[w];
    const float rstd = rsqrtf(vtot * (1.0f / D_) + 1e-5f);

    float4 gv = *(const float4*)(g + tid * 4);
    float4 bv = *(const float4*)(b + tid * 4);
    const size_t off = (size_t)row * D_ + tid * 4;
    uint2 pk;
    pk.x = pack_h2(d0 * rstd * gv.x + bv.x, d1 * rstd * gv.y + bv.y);
    pk.y = pack_h2(d2 * rstd * gv.z + bv.z, d3 * rstd * gv.w + bv.w);
    *(uint2*)(o + off) = pk;
}

// ------------------------- weight transpose + fp16 --------------------------
__global__ __launch_bounds__(256) void thalf_kernel(
    const float* __restrict__ W, __half* __restrict__ T, int K, int N)
{
    __shared__ float t[32][33];
    const int tx = threadIdx.x, ty = threadIdx.y;
    const int n0 = blockIdx.x * 32, k0 = blockIdx.y * 32;
    #pragma unroll
    for (int r = 0; r < 4; r++)
        t[ty + r*8][tx] = W[(size_t)(k0 + ty + r*8) * N + n0 + tx];
    __syncthreads();
    #pragma unroll
    for (int r = 0; r < 4; r++)
        T[(size_t)(n0 + ty + r*8) * K + k0 + tx] = __float2half_rn(t[tx][ty + r*8]);
}

__global__ void pack_bias_kernel(const float* __restrict__ bq,
                                 const float* __restrict__ bk,
                                 const float* __restrict__ bv,
                                 float* __restrict__ o)
{
    const int i = blockIdx.x * 256 + threadIdx.x;
    if (i < 1024)       o[i] = bq[i];
    else if (i < 2048)  o[i] = bk[i - 1024];
    else                o[i] = bv[i - 2048];
}

// ------------------------- fp16 HMMA GEMM -----------------------------------
// C[M,N] = A[M,K] @ W[K,N]; A fp16 [M,K], W^T fp16 [N,K].
// 128x128 CTA tile, BK=64 chunk, 8 warps (64x32 warp tiles), 2-stage cp.async,
// single __syncthreads per chunk.
// Smem tile: 128 rows x (64+8) halves (144 B row stride).
// OUT: 0 = fp32 (+res), 2 = packed fp16.
#define TROWB 144
#define TILEB (128*TROWB)          // 18432
#define STAGEB (2*TILEB)           // 36864
#define GSMEM  (2*STAGEB)          // 73728

template<int OUT, bool RELU, bool RES, bool QKVA>
__global__ __launch_bounds__(256, 2) void h16_gemm(
    const __half* __restrict__ A, const __half* __restrict__ Bw,
    const float* __restrict__ bias, const float* __restrict__ res,
    float* __restrict__ C, __half* __restrict__ Cb, int M, int N, int K)
{
    extern __shared__ char smem[];
    const u32 sbase = smem_u32(smem);

    const int tid = threadIdx.x;
    const int wid = tid >> 5;
    const int lid = tid & 31;
    const int wr  = wid & 1;
    const int wc  = wid >> 1;
    const int bm  = blockIdx.y * 128;
    const int bn  = blockIdx.x * 128;

    const __half* srcs[2] = {A, Bw};
    const int     rb  [2] = {bm, bn};
    const int nch = K >> 6;

    // 8 cp.async(16B) per thread per stage: 2 tiles x 128 rows x 8 segs
    int l_tile[8];
    size_t l_grow[8];
    int l_seg[8];
    u32 l_sm[8];
    #pragma unroll
    for (int it = 0; it < 8; it++) {
        const int idx = tid + it * 256;
        const int tile = idx >> 10;
        const int r    = (idx >> 3) & 127;
        const int seg  = idx & 7;
        l_tile[it] = tile;
        l_seg[it]  = seg;
        l_grow[it] = (size_t)(rb[tile] + r);
        l_sm[it]   = tile * TILEB + r * TROWB + seg * 16;
    }

    auto load_chunk = [&](int i, int st) {
        const size_t kc = (size_t)i * 64;
        const u32 so = sbase + st * STAGEB;
        #pragma unroll
        for (int it = 0; it < 8; it++) {
            const __half* gp = srcs[l_tile[it]] + l_grow[it] * (size_t)K + kc + l_seg[it] * 8;
            CP_ASYNC16(so + l_sm[it], gp);
        }
        CP_COMMIT();
    };

    float acc[4][4][4];
    #pragma unroll
    for (int i = 0; i < 4; i++)
        #pragma unroll
        for (int j = 0; j < 4; j++)
            #pragma unroll
            for (int f = 0; f < 4; f++) acc[i][j][f] = 0.f;

    const u32 a_lane = (u32)((wr*64 + (lid & 15)) * TROWB + (lid >> 4) * 16);
    const u32 b_lane = (u32)((wc*32 + (lid & 15)) * TROWB + (lid >> 4) * 16);

    load_chunk(0, 0);

    for (int i = 0; i < nch; i++) {
        const int st = i & 1;
        CP_WAIT(0);
        __syncthreads();
        if (i + 1 < nch) load_chunk(i + 1, st ^ 1);

        const u32 so = sbase + st * STAGEB;
        const u32 aB = so + a_lane;
        const u32 bB = so + TILEB + b_lane;

        #pragma unroll
        for (int ks = 0; ks < 4; ks++) {
            const u32 ko = ks * 32;   // 16 halves
            u32 fa[4][4];
            #pragma unroll
            for (int am = 0; am < 4; am++)
                LDSM_X4(fa[am][0], fa[am][1], fa[am][2], fa[am][3],
                        aB + am * (16*TROWB) + ko);
            u32 fb[4][2];
            #pragma unroll
            for (int bt2 = 0; bt2 < 2; bt2++) {
                u32 r0, r1, r2, r3;
                LDSM_X4(r0, r1, r2, r3, bB + bt2 * (16*TROWB) + ko);
                fb[bt2*2  ][0] = r0; fb[bt2*2  ][1] = r2;
                fb[bt2*2+1][0] = r1; fb[bt2*2+1][1] = r3;
            }
            #pragma unroll
            for (int am = 0; am < 4; am++)
                #pragma unroll
                for (int nt = 0; nt < 4; nt++)
                    MMA_F16(acc[am][nt], fa[am], fb[nt]);
        }
    }

    const int r0 = bm + wr*64 + (lid >> 2);
    const int c0 = bn + wc*32 + (lid & 3) * 2;
    #pragma unroll
    for (int am = 0; am < 4; am++) {
        #pragma unroll
        for (int bt = 0; bt < 4; bt++) {
            const int col = c0 + bt * 8;
            const float2 bv = *(const float2*)(bias + col);
            const float alpha = QKVA ? ((col < 1024) ? 0.125f : 1.0f) : 1.0f;
            #pragma unroll
            for (int half = 0; half < 2; half++) {
                const int row = r0 + am*16 + half*8;
                float v0 = (acc[am][bt][half*2 + 0] + bv.x) * alpha;
                float v1 = (acc[am][bt][half*2 + 1] + bv.y) * alpha;
                if (RELU) { v0 = fmaxf(v0, 0.f); v1 = fmaxf(v1, 0.f); }
                if (RES) {
                    const float2 rr = *(const float2*)(res + (size_t)row * N + col);
                    v0 += rr.x; v1 += rr.y;
                }
                if (OUT == 2) {
                    *(u32*)(Cb + (size_t)row * N + col) = pack_h2(v0, v1);
                } else {
                    float2 o; o.x = v0; o.y = v1;
                    *(float2*)(C + (size_t)row * N + col) = o;
                }
            }
        }
    }
}

// ------------------------- fp16 HMMA flash attention -------------------------
// Q/K/V are column slices of packed fp16 QKV (row stride QKVN). Q pre-scaled.
// Single __syncthreads per KV tile; mask via cp.async (raw ints in smem).
#define AQ_OFF   0
#define AK_OFF(st) (18432 + (st)*9216)
#define AV_OFF(st) (36864 + (st)*9216)
#define AM_OFF(st) (55296 + (st)*256)
#define ASMEM    55808

__global__ __launch_bounds__(256) void attn_mma_kernel(
    const __half* __restrict__ QKV, const int* __restrict__ mask,
    __half* __restrict__ O)
{
    extern __shared__ char sm[];
    const u32 sb = smem_u32(sm);
    const int tid = threadIdx.x;
    const int wid = tid >> 5;
    const int lid = tid & 31;
    const int h = blockIdx.y;
    const int b = blockIdx.z;
    const size_t qrow0 = (size_t)(b * S_ + blockIdx.x * 128);

    const __half* Q = QKV;
    const __half* K = QKV + 1024;
    const __half* V = QKV + 2048;

    for (int t = tid; t < 1024; t += 256) {
        const int r = t >> 3, cseg = t & 7;
        const uint4 v = *(const uint4*)(Q + (qrow0 + r) * QKVN + h * 64 + cseg * 8);
        *(uint4*)(sm + AQ_OFF + r * 144 + cseg * 16) = v;
    }

    auto load_kv = [&](int jt, int st) {
        const size_t krow0 = (size_t)(b * S_ + jt * 64);
        #pragma unroll
        for (int it = 0; it < 4; it++) {
            const int t = tid + it * 256;
            const int tile = t >> 9;
            const int r = (t >> 3) & 63;
            const int cseg = t & 7;
            const __half* src = (tile ? V : K) + (krow0 + r) * QKVN + h * 64 + cseg * 8;
            const u32 dst = sb + (tile ? AV_OFF(st) : AK_OFF(st)) + (u32)(r * 144 + cseg * 16);
            CP_ASYNC16(dst, src);
        }
        if (tid < 64)
            CP_ASYNC4(sb + AM_OFF(st) + tid * 4, mask + b * S_ + jt * 64 + tid);
        CP_COMMIT();
    };

    load_kv(0, 0);
    __syncthreads();   // Q staging visible

    u32 qf[4][4];
    const u32 qaddr = sb + AQ_OFF + (u32)((wid * 16 + (lid & 15)) * 144 + (lid >> 4) * 16);
    #pragma unroll
    for (int ks = 0; ks < 4; ks++)
        LDSM_X4(qf[ks][0], qf[ks][1], qf[ks][2], qf[ks][3], qaddr + ks * 32);

    float m0 = -INFINITY, m1 = -INFINITY, l0 = 0.f, l1 = 0.f;
    float o[8][4];
    #pragma unroll
    for (int t = 0; t < 8; t++)
        #pragma unroll
        for (int f = 0; f < 4; f++) o[t][f] = 0.f;

    const int ntiles = S_ / 64;
    for (int jt = 0; jt < ntiles; jt++) {
        const int st = jt & 1;
        CP_WAIT(0);
        __syncthreads();
        if (jt + 1 < ntiles) load_kv(jt + 1, st ^ 1);

        float s[8][4];
        #pragma unroll
        for (int t = 0; t < 8; t++)
            #pragma unroll
            for (int f = 0; f < 4; f++) s[t][f] = 0.f;

        const u32 kaddr = sb + AK_OFF(st) + (u32)(((lid & 15)) * 144 + (lid >> 4) * 16);
        #pragma unroll
        for (int ks = 0; ks < 4; ks++) {
            #pragma unroll
            for (int nt2 = 0; nt2 < 4; nt2++) {
                u32 r0, r1, r2, r3;
                LDSM_X4(r0, r1, r2, r3, kaddr + nt2 * (16*144) + ks * 32);
                u32 bA[2] = {r0, r2};
                u32 bB[2] = {r1, r3};
                MMA_F16(s[nt2*2],     qf[ks], bA);
                MMA_F16(s[nt2*2 + 1], qf[ks], bB);
            }
        }

        float mx0 = -INFINITY, mx1 = -INFINITY;
        #pragma unroll
        for (int t = 0; t < 8; t++) {
            const int mi_a = *(const int*)(sm + AM_OFF(st) + (t*8 + (lid & 3)*2) * 4);
            const int mi_b = *(const int*)(sm + AM_OFF(st) + (t*8 + (lid & 3)*2 + 1) * 4);
            const float ma = mi_a ? 0.f : -1e9f;
            const float mb = mi_b ? 0.f : -1e9f;
            s[t][0] += ma; s[t][1] += mb; s[t][2] += ma; s[t][3] += mb;
            mx0 = fmaxf(mx0, fmaxf(s[t][0], s[t][1]));
            mx1 = fmaxf(mx1, fmaxf(s[t][2], s[t][3]));
        }
        mx0 = fmaxf(mx0, __shfl_xor_sync(0xffffffffu, mx0, 1));
        mx0 = fmaxf(mx0, __shfl_xor_sync(0xffffffffu, mx0, 2));
        mx1 = fmaxf(mx1, __shfl_xor_sync(0xffffffffu, mx1, 1));
        mx1 = fmaxf(mx1, __shfl_xor_sync(0xffffffffu, mx1, 2));

        const float nm0 = fmaxf(m0, mx0);
        const float nm1 = fmaxf(m1, mx1);
        const float f0 = __expf(m0 - nm0);
        const float f1 = __expf(m1 - nm1);
        m0 = nm0; m1 = nm1;
        l0 *= f0;  l1 *= f1;
        #pragma unroll
        for (int t = 0; t < 8; t++) {
            o[t][0] *= f0; o[t][1] *= f0;
            o[t][2] *= f1; o[t][3] *= f1;
        }

        u32 pa[4][4];
        float ps0 = 0.f, ps1 = 0.f;
        #pragma unroll
        for (int t = 0; t < 8; t++) {
            const float p0 = __expf(s[t][0] - m0);
            const float p1 = __expf(s[t][1] - m0);
            const float p2 = __expf(s[t][2] - m1);
            const float p3 = __expf(s[t][3] - m1);
            ps0 += p0 + p1; ps1 += p2 + p3;
            pa[t >> 1][(t & 1) * 2]     = pack_h2(p0, p1);
            pa[t >> 1][(t & 1) * 2 + 1] = pack_h2(p2, p3);
        }
        ps0 += __shfl_xor_sync(0xffffffffu, ps0, 1);
        ps0 += __shfl_xor_sync(0xffffffffu, ps0, 2);
        ps1 += __shfl_xor_sync(0xffffffffu, ps1, 1);
        ps1 += __shfl_xor_sync(0xffffffffu, ps1, 2);
        l0 += ps0; l1 += ps1;

        const u32 vaddr = sb + AV_OFF(st) + (u32)(((lid & 15)) * 144 + (lid >> 4) * 16);
        #pragma unroll
        for (int ks = 0; ks < 4; ks++) {
            #pragma unroll
            for (int dt2 = 0; dt2 < 4; dt2++) {
                u32 r0, r1, r2, r3;
                LDSM_X4_T(r0, r1, r2, r3, vaddr + ks * (16*144) + dt2 * 32);
                u32 bA[2] = {r0, r1};
                u32 bB[2] = {r2, r3};
                MMA_F16(o[dt2*2],     pa[ks], bA);
                MMA_F16(o[dt2*2 + 1], pa[ks], bB);
            }
        }
    }

    const float inv0 = (l0 > 0.f) ? 1.f / l0 : 0.f;
    const float inv1 = (l1 > 0.f) ? 1.f / l1 : 0.f;
    const size_t row0 = qrow0 + wid * 16 + (lid >> 2);
    const int colb = h * 64 + (lid & 3) * 2;
    #pragma unroll
    for (int t = 0; t < 8; t++) {
        const int col = colb + t * 8;
        *(u32*)(O + row0 * D_ + col)       = pack_h2(o[t][0] * inv0, o[t][1] * inv0);
        *(u32*)(O + (row0 + 8) * D_ + col) = pack_h2(o[t][2] * inv1, o[t][3] * inv1);
    }
}

// ------------------------- launch -------------------------------------------
extern "C" void kernel_launch(void* const* d_in, const int* in_sizes, int n_in,
                              void* d_out, int out_size)
{
    const float* x    = (const float*)d_in[0];
    const int*   mask = (const int*)  d_in[1];
    const float* wq   = (const float*)d_in[2];
    const float* bq   = (const float*)d_in[3];
    const float* wk   = (const float*)d_in[4];
    const float* bk   = (const float*)d_in[5];
    const float* wv   = (const float*)d_in[6];
    const float* bv   = (const float*)d_in[7];
    const float* wo   = (const float*)d_in[8];
    const float* bo   = (const float*)d_in[9];
    const float* g1   = (const float*)d_in[10];
    const float* be1  = (const float*)d_in[11];
    const float* g2   = (const float*)d_in[12];
    const float* be2  = (const float*)d_in[13];
    const float* w1   = (const float*)d_in[14];
    const float* bf1  = (const float*)d_in[15];
    const float* w2   = (const float*)d_in[16];
    const float* bf2  = (const float*)d_in[17];
    float* out = (float*)d_out;

    void* p;
    cudaGetSymbolAddress(&p, g_xn);    __half* xn    = (__half*)p;
    cudaGetSymbolAddress(&p, g_qkv);   __half* qkv   = (__half*)p;
    cudaGetSymbolAddress(&p, g_att);   __half* att   = (__half*)p;
    cudaGetSymbolAddress(&p, g_x2);    float*  x2    = (float*)p;
    cudaGetSymbolAddress(&p, g_h);     __half* hb    = (__half*)p;
    cudaGetSymbolAddress(&p, g_wqkvT); __half* wqkvT = (__half*)p;
    cudaGetSymbolAddress(&p, g_bqkv);  float*  bqkv  = (float*)p;
    cudaGetSymbolAddress(&p, g_woT);   __half* woT   = (__half*)p;
    cudaGetSymbolAddress(&p, g_w1T);   __half* w1T   = (__half*)p;
    cudaGetSymbolAddress(&p, g_w2T);   __half* w2T   = (__half*)p;

    cudaFuncSetAttribute(h16_gemm<2,false,false,true >, cudaFuncAttributeMaxDynamicSharedMemorySize, GSMEM);
    cudaFuncSetAttribute(h16_gemm<0,false,true ,false>, cudaFuncAttributeMaxDynamicSharedMemorySize, GSMEM);
    cudaFuncSetAttribute(h16_gemm<2,true ,false,false>, cudaFuncAttributeMaxDynamicSharedMemorySize, GSMEM);
    cudaFuncSetAttribute(attn_mma_kernel, cudaFuncAttributeMaxDynamicSharedMemorySize, ASMEM);

    const dim3 tb(32, 8);
    thalf_kernel<<<dim3(D_/32, D_/32), tb>>>(wq, wqkvT,           D_, D_);
    thalf_kernel<<<dim3(D_/32, D_/32), tb>>>(wk, wqkvT + 1024*D_, D_, D_);
    thalf_kernel<<<dim3(D_/32, D_/32), tb>>>(wv, wqkvT + 2048*D_, D_, D_);
    thalf_kernel<<<dim3(D_/32, D_/32), tb>>>(wo, woT, D_, D_);
    thalf_kernel<<<dim3(F_/32, D_/32), tb>>>(w1, w1T, D_, F_);
    thalf_kernel<<<dim3(D_/32, F_/32), tb>>>(w2, w2T, F_, D_);
    pack_bias_kernel<<<QKVN/256, 256>>>(bq, bk, bv, bqkv);

    ln_kernel<<<M_, 256>>>(x, g1, be1, xn);

    // fused QKV GEMM -> packed fp16 [M, 3072] (Q cols pre-scaled by 1/8)
    const dim3 gQKV(QKVN/128, M_/128);
    h16_gemm<2,false,false,true><<<gQKV, 256, GSMEM>>>(xn, wqkvT, bqkv, nullptr, nullptr, qkv, M_, QKVN, D_);

    dim3 attG(S_/128, H_, B_);
    attn_mma_kernel<<<attG, 256, ASMEM>>>(qkv, mask, att);

    const dim3 gD(D_/128, M_/128);
    h16_gemm<0,false,true,false><<<gD, 256, GSMEM>>>(att, woT, bo, x, x2, nullptr, M_, D_, D_);

    ln_kernel<<<M_, 256>>>(x2, g2, be2, xn);

    const dim3 gF(F_/128, M_/128);
    h16_gemm<2,true,false,false><<<gF, 256, GSMEM>>>(xn, w1T, bf1, nullptr, nullptr, hb, M_, F_, D_);

    h16_gemm<0,false,true,false><<<gD, 256, GSMEM>>>(hb, w2T, bf2, x2, out, nullptr, M_, D_, F_);
}

// round 9
// speedup vs baseline: 8.0911x; 1.1545x over previous
#include <cuda_runtime.h>
#include <cuda_fp16.h>
#include <math.h>

typedef unsigned int u32;
typedef unsigned long long u64;

#define B_   2
#define S_   2048
#define D_   1024
#define H_   16
#define F_   4096
#define M_   (B_*S_)
#define QKVN 3072

// ------------------------- scratch (device globals) -------------------------
__device__ __align__(16) __half g_xn[M_*D_];
__device__ __align__(16) __half g_qkv[(size_t)M_*QKVN];
__device__ __align__(16) __half g_att[M_*D_];
__device__ __align__(16) float  g_x2[M_*D_];
__device__ __align__(16) __half g_h[(size_t)M_*F_];
__device__ __align__(16) __half g_wqkv16[(size_t)D_*QKVN];  // [K=1024][N=3072]
__device__ __align__(16) float  g_bqkv[QKVN];
__device__ __align__(16) __half g_wo16[D_*D_];              // [K][N]
__device__ __align__(16) __half g_w116[(size_t)D_*F_];      // [1024][4096]
__device__ __align__(16) __half g_w216[(size_t)F_*D_];      // [4096][1024]

// ------------------------- helpers ------------------------------------------
__device__ __forceinline__ u32 smem_u32(const void* p) {
    u32 a;
    asm("{ .reg .u64 t; cvta.to.shared.u64 t, %1; cvt.u32.u64 %0, t; }"
        : "=r"(a) : "l"(p));
    return a;
}
#define CP_ASYNC16(sm, gp) \
    asm volatile("cp.async.cg.shared.global [%0], [%1], 16;" :: "r"(sm), "l"(gp))
#define CP_ASYNC4(sm, gp) \
    asm volatile("cp.async.ca.shared.global [%0], [%1], 4;" :: "r"(sm), "l"(gp))
#define CP_COMMIT() asm volatile("cp.async.commit_group;" ::: "memory")
#define CP_WAIT(n)  asm volatile("cp.async.wait_group %0;" :: "n"(n) : "memory")

#define LDSM_X4(r0,r1,r2,r3,a) \
    asm volatile("ldmatrix.sync.aligned.m8n8.x4.shared.b16 {%0,%1,%2,%3}, [%4];" \
        : "=r"(r0), "=r"(r1), "=r"(r2), "=r"(r3) : "r"(a))
#define LDSM_X4_T(r0,r1,r2,r3,a) \
    asm volatile("ldmatrix.sync.aligned.m8n8.x4.trans.shared.b16 {%0,%1,%2,%3}, [%4];" \
        : "=r"(r0), "=r"(r1), "=r"(r2), "=r"(r3) : "r"(a))

#define MMA_F16(d, a, b) \
    asm volatile("mma.sync.aligned.m16n8k16.row.col.f32.f16.f16.f32 " \
        "{%0,%1,%2,%3}, {%4,%5,%6,%7}, {%8,%9}, {%0,%1,%2,%3};" \
        : "+f"((d)[0]), "+f"((d)[1]), "+f"((d)[2]), "+f"((d)[3]) \
        : "r"((a)[0]), "r"((a)[1]), "r"((a)[2]), "r"((a)[3]), \
          "r"((b)[0]), "r"((b)[1]))

__device__ __forceinline__ u32 pack_h2(float a, float b) {
    __half2 t = __floats2half2_rn(a, b);
    return *(u32*)&t;
}

// ------------------------- layernorm (fp16 out) ------------------------------
__global__ __launch_bounds__(256) void ln_kernel(
    const float* __restrict__ x, const float* __restrict__ g,
    const float* __restrict__ b, __half* __restrict__ o)
{
    __shared__ float red[8];
    const int row = blockIdx.x;
    const int tid = threadIdx.x;
    const float* xr = x + (size_t)row * D_;

    float4 xv = *(const float4*)(xr + tid * 4);
    float s = xv.x + xv.y + xv.z + xv.w;
    #pragma unroll
    for (int of = 16; of > 0; of >>= 1) s += __shfl_xor_sync(0xffffffffu, s, of);
    if ((tid & 31) == 0) red[tid >> 5] = s;
    __syncthreads();
    float tot = 0.f;
    #pragma unroll
    for (int w = 0; w < 8; w++) tot += red[w];
    const float mean = tot * (1.0f / D_);

    float d0 = xv.x - mean, d1 = xv.y - mean, d2 = xv.z - mean, d3 = xv.w - mean;
    float sq = d0*d0 + d1*d1 + d2*d2 + d3*d3;
    __syncthreads();
    #pragma unroll
    for (int of = 16; of > 0; of >>= 1) sq += __shfl_xor_sync(0xffffffffu, sq, of);
    if ((tid & 31) == 0) red[tid >> 5] = sq;
    __syncthreads();
    float vtot = 0.f;
    #pragma unroll
    for (int w = 0; w < 8; w++) vtot += red[w];
    const float rstd = rsqrtf(vtot * (1.0f / D_) + 1e-5f);

    float4 gv = *(const float4*)(g + tid * 4);
    float4 bv = *(const float4*)(b + tid * 4);
    const size_t off = (size_t)row * D_ + tid * 4;
    uint2 pk;
    pk.x = pack_h2(d0 * rstd * gv.x + bv.x, d1 * rstd * gv.y + bv.y);
    pk.y = pack_h2(d2 * rstd * gv.z + bv.z, d3 * rstd * gv.w + bv.w);
    *(uint2*)(o + off) = pk;
}

// ------------------------- fused weight fp32->fp16 convert -------------------
// One launch, 6 jobs (blockIdx.y). QKV packed column-wise into [1024][3072].
__global__ __launch_bounds__(256) void convert_w_kernel(
    const float* __restrict__ wq, const float* __restrict__ wk,
    const float* __restrict__ wv, const float* __restrict__ wo,
    const float* __restrict__ w1, const float* __restrict__ w2,
    __half* __restrict__ wqkv, __half* __restrict__ wo16,
    __half* __restrict__ w116, __half* __restrict__ w216)
{
    const int job = blockIdx.y;
    const float* src; __half* dst;
    int shift, dstStride, colOff, total;
    switch (job) {
        case 0: src=wq; dst=wqkv; shift=10; dstStride=QKVN; colOff=0;    total=1<<20; break;
        case 1: src=wk; dst=wqkv; shift=10; dstStride=QKVN; colOff=1024; total=1<<20; break;
        case 2: src=wv; dst=wqkv; shift=10; dstStride=QKVN; colOff=2048; total=1<<20; break;
        case 3: src=wo; dst=wo16; shift=10; dstStride=1024; colOff=0;    total=1<<20; break;
        case 4: src=w1; dst=w116; shift=12; dstStride=4096; colOff=0;    total=1<<22; break;
        default:src=w2; dst=w216; shift=10; dstStride=1024; colOff=0;    total=1<<22; break;
    }
    const int cmask = (1 << shift) - 1;
    for (int e = (blockIdx.x * 256 + threadIdx.x) * 4; e < total; e += gridDim.x * 1024) {
        const float4 v = *(const float4*)(src + e);
        const int row = e >> shift;
        const int col = e & cmask;
        uint2 pk;
        pk.x = pack_h2(v.x, v.y);
        pk.y = pack_h2(v.z, v.w);
        *(uint2*)(dst + (size_t)row * dstStride + colOff + col) = pk;
    }
}

__global__ void pack_bias_kernel(const float* __restrict__ bq,
                                 const float* __restrict__ bk,
                                 const float* __restrict__ bv,
                                 float* __restrict__ o)
{
    const int i = blockIdx.x * 256 + threadIdx.x;
    if (i < 1024)       o[i] = bq[i];
    else if (i < 2048)  o[i] = bk[i - 1024];
    else                o[i] = bv[i - 2048];
}

// ------------------------- fp16 HMMA GEMM -----------------------------------
// C[M,N] = A[M,K] @ W[K,N]; A fp16 [M,K], W fp16 [K,N] (natural layout).
// 128x128 CTA tile, BK=64 chunk, 8 warps (64x32 warp tiles), 2-stage cp.async,
// single __syncthreads per chunk. B fragments via ldmatrix.trans.
// A smem: 128 rows x 144 B. B smem: 64 K-rows x 272 B (256 data + 16 pad).
// OUT: 0 = fp32 (+res), 2 = packed fp16.
#define ATROWB 144
#define ATILE  (128*ATROWB)        // 18432
#define BROWB  272
#define BTILE  (64*BROWB)          // 17408
#define STAGEB (ATILE + BTILE)     // 35840
#define GSMEM  (2*STAGEB)          // 71680

template<int OUT, bool RELU, bool RES, bool QKVA>
__global__ __launch_bounds__(256, 2) void h16_gemm(
    const __half* __restrict__ A, const __half* __restrict__ Bw,
    const float* __restrict__ bias, const float* __restrict__ res,
    float* __restrict__ C, __half* __restrict__ Cb, int M, int N, int K)
{
    extern __shared__ char smem[];
    const u32 sbase = smem_u32(smem);

    const int tid = threadIdx.x;
    const int wid = tid >> 5;
    const int lid = tid & 31;
    const int wr  = wid & 1;
    const int wc  = wid >> 1;
    const int bm  = blockIdx.y * 128;
    const int bn  = blockIdx.x * 128;

    const int nch = K >> 6;

    auto load_chunk = [&](int i, int st) {
        const size_t kc = (size_t)i * 64;
        const u32 so = sbase + st * STAGEB;
        // A tile: 128 rows x 8 segs of 16B
        #pragma unroll
        for (int it = 0; it < 4; it++) {
            const int idx = tid + it * 256;
            const int r = idx >> 3, seg = idx & 7;
            const __half* gp = A + (size_t)(bm + r) * K + kc + seg * 8;
            CP_ASYNC16(so + r * ATROWB + seg * 16, gp);
        }
        // B tile: 64 K-rows x 16 segs of 16B (128 N cols)
        #pragma unroll
        for (int it = 0; it < 4; it++) {
            const int idx = tid + it * 256;
            const int r = idx >> 4, seg = idx & 15;
            const __half* gp = Bw + (kc + r) * (size_t)N + bn + seg * 8;
            CP_ASYNC16(so + ATILE + r * BROWB + seg * 16, gp);
        }
        CP_COMMIT();
    };

    float acc[4][4][4];
    #pragma unroll
    for (int i = 0; i < 4; i++)
        #pragma unroll
        for (int j = 0; j < 4; j++)
            #pragma unroll
            for (int f = 0; f < 4; f++) acc[i][j][f] = 0.f;

    const u32 a_lane = (u32)((wr*64 + (lid & 15)) * ATROWB + (lid >> 4) * 16);
    const u32 b_lane = (u32)((lid & 15) * BROWB + (lid >> 4) * 16 + wc * 64);

    load_chunk(0, 0);

    for (int i = 0; i < nch; i++) {
        const int st = i & 1;
        CP_WAIT(0);
        __syncthreads();
        if (i + 1 < nch) load_chunk(i + 1, st ^ 1);

        const u32 so = sbase + st * STAGEB;
        const u32 aB = so + a_lane;
        const u32 bB = so + ATILE + b_lane;

        #pragma unroll
        for (int ks = 0; ks < 4; ks++) {
            u32 fa[4][4];
            #pragma unroll
            for (int am = 0; am < 4; am++)
                LDSM_X4(fa[am][0], fa[am][1], fa[am][2], fa[am][3],
                        aB + am * (16*ATROWB) + ks * 32);
            u32 fb[4][2];
            #pragma unroll
            for (int ns = 0; ns < 2; ns++) {
                u32 r0, r1, r2, r3;
                LDSM_X4_T(r0, r1, r2, r3, bB + ks * (16*BROWB) + ns * 32);
                fb[ns*2  ][0] = r0; fb[ns*2  ][1] = r1;
                fb[ns*2+1][0] = r2; fb[ns*2+1][1] = r3;
            }
            #pragma unroll
            for (int am = 0; am < 4; am++)
                #pragma unroll
                for (int nt = 0; nt < 4; nt++)
                    MMA_F16(acc[am][nt], fa[am], fb[nt]);
        }
    }

    const int r0 = bm + wr*64 + (lid >> 2);
    const int c0 = bn + wc*32 + (lid & 3) * 2;
    #pragma unroll
    for (int am = 0; am < 4; am++) {
        #pragma unroll
        for (int bt = 0; bt < 4; bt++) {
            const int col = c0 + bt * 8;
            const float2 bv = *(const float2*)(bias + col);
            const float alpha = QKVA ? ((col < 1024) ? 0.125f : 1.0f) : 1.0f;
            #pragma unroll
            for (int half = 0; half < 2; half++) {
                const int row = r0 + am*16 + half*8;
                float v0 = (acc[am][bt][half*2 + 0] + bv.x) * alpha;
                float v1 = (acc[am][bt][half*2 + 1] + bv.y) * alpha;
                if (RELU) { v0 = fmaxf(v0, 0.f); v1 = fmaxf(v1, 0.f); }
                if (RES) {
                    const float2 rr = *(const float2*)(res + (size_t)row * N + col);
                    v0 += rr.x; v1 += rr.y;
                }
                if (OUT == 2) {
                    *(u32*)(Cb + (size_t)row * N + col) = pack_h2(v0, v1);
                } else {
                    float2 o; o.x = v0; o.y = v1;
                    *(float2*)(C + (size_t)row * N + col) = o;
                }
            }
        }
    }
}

// ------------------------- fp16 HMMA flash attention -------------------------
#define AQ_OFF   0
#define AK_OFF(st) (18432 + (st)*9216)
#define AV_OFF(st) (36864 + (st)*9216)
#define AM_OFF(st) (55296 + (st)*256)
#define ASMEM    55808

__global__ __launch_bounds__(256, 2) void attn_mma_kernel(
    const __half* __restrict__ QKV, const int* __restrict__ mask,
    __half* __restrict__ O)
{
    extern __shared__ char sm[];
    const u32 sb = smem_u32(sm);
    const int tid = threadIdx.x;
    const int wid = tid >> 5;
    const int lid = tid & 31;
    const int h = blockIdx.y;
    const int b = blockIdx.z;
    const size_t qrow0 = (size_t)(b * S_ + blockIdx.x * 128);

    const __half* Q = QKV;
    const __half* K = QKV + 1024;
    const __half* V = QKV + 2048;

    for (int t = tid; t < 1024; t += 256) {
        const int r = t >> 3, cseg = t & 7;
        const uint4 v = *(const uint4*)(Q + (qrow0 + r) * QKVN + h * 64 + cseg * 8);
        *(uint4*)(sm + AQ_OFF + r * 144 + cseg * 16) = v;
    }

    auto load_kv = [&](int jt, int st) {
        const size_t krow0 = (size_t)(b * S_ + jt * 64);
        #pragma unroll
        for (int it = 0; it < 4; it++) {
            const int t = tid + it * 256;
            const int tile = t >> 9;
            const int r = (t >> 3) & 63;
            const int cseg = t & 7;
            const __half* src = (tile ? V : K) + (krow0 + r) * QKVN + h * 64 + cseg * 8;
            const u32 dst = sb + (tile ? AV_OFF(st) : AK_OFF(st)) + (u32)(r * 144 + cseg * 16);
            CP_ASYNC16(dst, src);
        }
        if (tid < 64)
            CP_ASYNC4(sb + AM_OFF(st) + tid * 4, mask + b * S_ + jt * 64 + tid);
        CP_COMMIT();
    };

    load_kv(0, 0);
    __syncthreads();   // Q staging visible

    u32 qf[4][4];
    const u32 qaddr = sb + AQ_OFF + (u32)((wid * 16 + (lid & 15)) * 144 + (lid >> 4) * 16);
    #pragma unroll
    for (int ks = 0; ks < 4; ks++)
        LDSM_X4(qf[ks][0], qf[ks][1], qf[ks][2], qf[ks][3], qaddr + ks * 32);

    float m0 = -INFINITY, m1 = -INFINITY, l0 = 0.f, l1 = 0.f;
    float o[8][4];
    #pragma unroll
    for (int t = 0; t < 8; t++)
        #pragma unroll
        for (int f = 0; f < 4; f++) o[t][f] = 0.f;

    const int ntiles = S_ / 64;
    for (int jt = 0; jt < ntiles; jt++) {
        const int st = jt & 1;
        CP_WAIT(0);
        __syncthreads();
        if (jt + 1 < ntiles) load_kv(jt + 1, st ^ 1);

        float s[8][4];
        #pragma unroll
        for (int t = 0; t < 8; t++)
            #pragma unroll
            for (int f = 0; f < 4; f++) s[t][f] = 0.f;

        const u32 kaddr = sb + AK_OFF(st) + (u32)(((lid & 15)) * 144 + (lid >> 4) * 16);
        #pragma unroll
        for (int ks = 0; ks < 4; ks++) {
            #pragma unroll
            for (int nt2 = 0; nt2 < 4; nt2++) {
                u32 r0, r1, r2, r3;
                LDSM_X4(r0, r1, r2, r3, kaddr + nt2 * (16*144) + ks * 32);
                u32 bA[2] = {r0, r2};
                u32 bB[2] = {r1, r3};
                MMA_F16(s[nt2*2],     qf[ks], bA);
                MMA_F16(s[nt2*2 + 1], qf[ks], bB);
            }
        }

        float mx0 = -INFINITY, mx1 = -INFINITY;
        #pragma unroll
        for (int t = 0; t < 8; t++) {
            const int mi_a = *(const int*)(sm + AM_OFF(st) + (t*8 + (lid & 3)*2) * 4);
            const int mi_b = *(const int*)(sm + AM_OFF(st) + (t*8 + (lid & 3)*2 + 1) * 4);
            const float ma = mi_a ? 0.f : -1e9f;
            const float mb = mi_b ? 0.f : -1e9f;
            s[t][0] += ma; s[t][1] += mb; s[t][2] += ma; s[t][3] += mb;
            mx0 = fmaxf(mx0, fmaxf(s[t][0], s[t][1]));
            mx1 = fmaxf(mx1, fmaxf(s[t][2], s[t][3]));
        }
        mx0 = fmaxf(mx0, __shfl_xor_sync(0xffffffffu, mx0, 1));
        mx0 = fmaxf(mx0, __shfl_xor_sync(0xffffffffu, mx0, 2));
        mx1 = fmaxf(mx1, __shfl_xor_sync(0xffffffffu, mx1, 1));
        mx1 = fmaxf(mx1, __shfl_xor_sync(0xffffffffu, mx1, 2));

        const float nm0 = fmaxf(m0, mx0);
        const float nm1 = fmaxf(m1, mx1);
        const float f0 = __expf(m0 - nm0);
        const float f1 = __expf(m1 - nm1);
        m0 = nm0; m1 = nm1;
        l0 *= f0;  l1 *= f1;
        #pragma unroll
        for (int t = 0; t < 8; t++) {
            o[t][0] *= f0; o[t][1] *= f0;
            o[t][2] *= f1; o[t][3] *= f1;
        }

        u32 pa[4][4];
        float ps0 = 0.f, ps1 = 0.f;
        #pragma unroll
        for (int t = 0; t < 8; t++) {
            const float p0 = __expf(s[t][0] - m0);
            const float p1 = __expf(s[t][1] - m0);
            const float p2 = __expf(s[t][2] - m1);
            const float p3 = __expf(s[t][3] - m1);
            ps0 += p0 + p1; ps1 += p2 + p3;
            pa[t >> 1][(t & 1) * 2]     = pack_h2(p0, p1);
            pa[t >> 1][(t & 1) * 2 + 1] = pack_h2(p2, p3);
        }
        ps0 += __shfl_xor_sync(0xffffffffu, ps0, 1);
        ps0 += __shfl_xor_sync(0xffffffffu, ps0, 2);
        ps1 += __shfl_xor_sync(0xffffffffu, ps1, 1);
        ps1 += __shfl_xor_sync(0xffffffffu, ps1, 2);
        l0 += ps0; l1 += ps1;

        const u32 vaddr = sb + AV_OFF(st) + (u32)(((lid & 15)) * 144 + (lid >> 4) * 16);
        #pragma unroll
        for (int ks = 0; ks < 4; ks++) {
            #pragma unroll
            for (int dt2 = 0; dt2 < 4; dt2++) {
                u32 r0, r1, r2, r3;
                LDSM_X4_T(r0, r1, r2, r3, vaddr + ks * (16*144) + dt2 * 32);
                u32 bA[2] = {r0, r1};
                u32 bB[2] = {r2, r3};
                MMA_F16(o[dt2*2],     pa[ks], bA);
                MMA_F16(o[dt2*2 + 1], pa[ks], bB);
            }
        }
    }

    const float inv0 = (l0 > 0.f) ? 1.f / l0 : 0.f;
    const float inv1 = (l1 > 0.f) ? 1.f / l1 : 0.f;
    const size_t row0 = qrow0 + wid * 16 + (lid >> 2);
    const int colb = h * 64 + (lid & 3) * 2;
    #pragma unroll
    for (int t = 0; t < 8; t++) {
        const int col = colb + t * 8;
        *(u32*)(O + row0 * D_ + col)       = pack_h2(o[t][0] * inv0, o[t][1] * inv0);
        *(u32*)(O + (row0 + 8) * D_ + col) = pack_h2(o[t][2] * inv1, o[t][3] * inv1);
    }
}

// ------------------------- launch -------------------------------------------
extern "C" void kernel_launch(void* const* d_in, const int* in_sizes, int n_in,
                              void* d_out, int out_size)
{
    const float* x    = (const float*)d_in[0];
    const int*   mask = (const int*)  d_in[1];
    const float* wq   = (const float*)d_in[2];
    const float* bq   = (const float*)d_in[3];
    const float* wk   = (const float*)d_in[4];
    const float* bk   = (const float*)d_in[5];
    const float* wv   = (const float*)d_in[6];
    const float* bv   = (const float*)d_in[7];
    const float* wo   = (const float*)d_in[8];
    const float* bo   = (const float*)d_in[9];
    const float* g1   = (const float*)d_in[10];
    const float* be1  = (const float*)d_in[11];
    const float* g2   = (const float*)d_in[12];
    const float* be2  = (const float*)d_in[13];
    const float* w1   = (const float*)d_in[14];
    const float* bf1  = (const float*)d_in[15];
    const float* w2   = (const float*)d_in[16];
    const float* bf2  = (const float*)d_in[17];
    float* out = (float*)d_out;

    void* p;
    cudaGetSymbolAddress(&p, g_xn);     __half* xn     = (__half*)p;
    cudaGetSymbolAddress(&p, g_qkv);    __half* qkv    = (__half*)p;
    cudaGetSymbolAddress(&p, g_att);    __half* att    = (__half*)p;
    cudaGetSymbolAddress(&p, g_x2);     float*  x2     = (float*)p;
    cudaGetSymbolAddress(&p, g_h);      __half* hb     = (__half*)p;
    cudaGetSymbolAddress(&p, g_wqkv16); __half* wqkv16 = (__half*)p;
    cudaGetSymbolAddress(&p, g_bqkv);   float*  bqkv   = (float*)p;
    cudaGetSymbolAddress(&p, g_wo16);   __half* wo16   = (__half*)p;
    cudaGetSymbolAddress(&p, g_w116);   __half* w116   = (__half*)p;
    cudaGetSymbolAddress(&p, g_w216);   __half* w216   = (__half*)p;

    cudaFuncSetAttribute(h16_gemm<2,false,false,true >, cudaFuncAttributeMaxDynamicSharedMemorySize, GSMEM);
    cudaFuncSetAttribute(h16_gemm<0,false,true ,false>, cudaFuncAttributeMaxDynamicSharedMemorySize, GSMEM);
    cudaFuncSetAttribute(h16_gemm<2,true ,false,false>, cudaFuncAttributeMaxDynamicSharedMemorySize, GSMEM);
    cudaFuncSetAttribute(attn_mma_kernel, cudaFuncAttributeMaxDynamicSharedMemorySize, ASMEM);

    // single fused weight conversion (no transpose) + bias pack + LN1
    convert_w_kernel<<<dim3(2048, 6), 256>>>(wq, wk, wv, wo, w1, w2,
                                             wqkv16, wo16, w116, w216);
    pack_bias_kernel<<<QKVN/256, 256>>>(bq, bk, bv, bqkv);
    ln_kernel<<<M_, 256>>>(x, g1, be1, xn);

    // fused QKV GEMM -> packed fp16 [M, 3072] (Q cols pre-scaled by 1/8)
    const dim3 gQKV(QKVN/128, M_/128);
    h16_gemm<2,false,false,true><<<gQKV, 256, GSMEM>>>(xn, wqkv16, bqkv, nullptr, nullptr, qkv, M_, QKVN, D_);

    dim3 attG(S_/128, H_, B_);
    attn_mma_kernel<<<attG, 256, ASMEM>>>(qkv, mask, att);

    const dim3 gD(D_/128, M_/128);
    h16_gemm<0,false,true,false><<<gD, 256, GSMEM>>>(att, wo16, bo, x, x2, nullptr, M_, D_, D_);

    ln_kernel<<<M_, 256>>>(x2, g2, be2, xn);

    const dim3 gF(F_/128, M_/128);
    h16_gemm<2,true,false,false><<<gF, 256, GSMEM>>>(xn, w116, bf1, nullptr, nullptr, hb, M_, F_, D_);

    h16_gemm<0,false,true,false><<<gD, 256, GSMEM>>>(hb, w216, bf2, x2, out, nullptr, M_, D_, F_);
}